// round 4
// baseline (speedup 1.0000x reference)
#include <cuda_runtime.h>
#include <math.h>

#define Tn   512
#define Bn   64
#define Hn   512
#define G4   2048
#define NOUT 128
#define NCTA_LSTM 128
#define NCHUNK 16          // 512 / 32

__device__ float g_xw[(size_t)2 * Tn * Bn * G4];
__device__ float g_out0[(size_t)Tn * Bn * 2 * Hn];
__device__ float g_out1[(size_t)Tn * Bn * 2 * Hn];
__device__ float g_hT[2 * 2 * Hn * Bn];
__device__ float g_attn[Bn * Tn];
__device__ unsigned g_barv[64];   // per-direction barrier counters (dir*32)

__device__ __forceinline__ unsigned long long pk2(float lo, float hi) {
    unsigned long long r;
    asm("mov.b64 %0, {%1, %2};" : "=l"(r) : "f"(lo), "f"(hi));
    return r;
}
__device__ __forceinline__ void fma2(unsigned long long& d, unsigned long long a, unsigned long long b) {
    asm("fma.rn.f32x2 %0, %1, %2, %0;" : "+l"(d) : "l"(a), "l"(b));
}
__device__ __forceinline__ float2 upk2(unsigned long long v) {
    float2 r;
    asm("mov.b64 {%0, %1}, %2;" : "=f"(r.x), "=f"(r.y) : "l"(v));
    return r;
}

// ============ GEMM: C[dir][m][n] = X[m][:] . W[dir][n][:] + b[dir][n] ============
#define GBM 128
#define GBN 128
#define GBK 16

__global__ __launch_bounds__(256, 2)
void gemm_xw_kernel(const float* __restrict__ X, const float* __restrict__ W,
                    const float* __restrict__ bias, float* __restrict__ C, int K) {
    const int N = G4, M = Tn * Bn;
    const int dir = blockIdx.z;
    const float* Wd = W + (size_t)dir * N * K;
    const float* bd = bias + (size_t)dir * N;
    float* Cd = C + (size_t)dir * M * N;

    __shared__ __align__(16) float As[GBK][GBM + 4];
    __shared__ __align__(16) float Bs[GBK][GBN + 4];

    const int tid = threadIdx.x;
    const int m0 = blockIdx.y * GBM;
    const int n0 = blockIdx.x * GBN;
    const int tx = tid & 15, ty = tid >> 4;
    const int lrow = tid >> 1;
    const int lk = (tid & 1) * 8;

    unsigned long long acc[8][4];
#pragma unroll
    for (int i = 0; i < 8; i++)
#pragma unroll
        for (int j = 0; j < 4; j++) acc[i][j] = 0ULL;

#pragma unroll 1
    for (int kt = 0; kt < K; kt += GBK) {
        float4 a0 = *(const float4*)(X + (size_t)(m0 + lrow) * K + kt + lk);
        float4 a1 = *(const float4*)(X + (size_t)(m0 + lrow) * K + kt + lk + 4);
        float4 b0 = *(const float4*)(Wd + (size_t)(n0 + lrow) * K + kt + lk);
        float4 b1 = *(const float4*)(Wd + (size_t)(n0 + lrow) * K + kt + lk + 4);
        __syncthreads();
        As[lk+0][lrow]=a0.x; As[lk+1][lrow]=a0.y; As[lk+2][lrow]=a0.z; As[lk+3][lrow]=a0.w;
        As[lk+4][lrow]=a1.x; As[lk+5][lrow]=a1.y; As[lk+6][lrow]=a1.z; As[lk+7][lrow]=a1.w;
        Bs[lk+0][lrow]=b0.x; Bs[lk+1][lrow]=b0.y; Bs[lk+2][lrow]=b0.z; Bs[lk+3][lrow]=b0.w;
        Bs[lk+4][lrow]=b1.x; Bs[lk+5][lrow]=b1.y; Bs[lk+6][lrow]=b1.z; Bs[lk+7][lrow]=b1.w;
        __syncthreads();
#pragma unroll
        for (int k = 0; k < GBK; k++) {
            float4 af0 = *(const float4*)&As[k][ty * 8];
            float4 af1 = *(const float4*)&As[k][ty * 8 + 4];
            ulonglong2 bp0 = *(const ulonglong2*)&Bs[k][tx * 8];
            ulonglong2 bp1 = *(const ulonglong2*)&Bs[k][tx * 8 + 4];
            float a[8] = {af0.x, af0.y, af0.z, af0.w, af1.x, af1.y, af1.z, af1.w};
            unsigned long long b2[4] = {bp0.x, bp0.y, bp1.x, bp1.y};
#pragma unroll
            for (int i = 0; i < 8; i++) {
                unsigned long long ad = pk2(a[i], a[i]);
                fma2(acc[i][0], ad, b2[0]);
                fma2(acc[i][1], ad, b2[1]);
                fma2(acc[i][2], ad, b2[2]);
                fma2(acc[i][3], ad, b2[3]);
            }
        }
    }
#pragma unroll
    for (int i = 0; i < 8; i++) {
        float* cp = Cd + (size_t)(m0 + ty * 8 + i) * G4 + n0 + tx * 8;
#pragma unroll
        for (int j = 0; j < 4; j++) {
            float2 v = upk2(acc[i][j]);
            v.x += bd[n0 + tx * 8 + 2 * j];
            v.y += bd[n0 + tx * 8 + 2 * j + 1];
            *(float2*)(cp + 2 * j) = v;
        }
    }
}

// ============ init: reset barriers + zero h state ============
__global__ void init_kernel() {
    int i = blockIdx.x * blockDim.x + threadIdx.x;
    if (i < 64) g_barv[i] = 0u;
    for (int j = i; j < 2 * 2 * Hn * Bn; j += gridDim.x * blockDim.x) g_hT[j] = 0.f;
}

// ============ persistent bidirectional LSTM layer (pipelined) ============
// smem (floats):
//  sW2: [512][32] u64 dup-packed weights   = 32768 floats (131072 B)
//  sH : 3 x [32][72] h chunk buffers       =  6912 floats
//  sX : [32][68] xw staging (next step)    =  2176 floats
//  sG : [32][66] gate preacts              =  2112 floats
//  sC : [8][64] cell state                 =   512 floats
#define SMF_W  32768
#define SMF_H  (3 * 32 * 72)
#define SMF_X  (32 * 68)
#define SMF_G  (32 * 66)
#define SMF_C  512
#define LSTM_SMEM_BYTES ((SMF_W + SMF_H + SMF_X + SMF_G + SMF_C) * 4)

__global__ __launch_bounds__(256)
void lstm_kernel(const float* __restrict__ xw, const float* __restrict__ Whh,
                 float* __restrict__ out) {
    extern __shared__ float sm[];
    unsigned long long* sW2 = (unsigned long long*)sm;      // [k][r] u64
    float* sH = sm + SMF_W;                                  // 3 bufs [32][72]
    float* sX = sH + SMF_H;                                  // [32][68]
    float* sG = sX + SMF_X;                                  // [32][66]
    float* sC = sG + SMF_G;                                  // [8][64]

    const int tid = threadIdx.x;
    const int dir = blockIdx.x >> 6;
    const int u0 = (blockIdx.x & 63) << 3;

    // ---- load + duplicate Whh slice (k-major, conflict-free LDS.64) ----
    for (int i = tid; i < 32 * 512; i += 256) {
        int r = i >> 9, k = i & 511;
        int gb = r >> 3, uu = u0 + (r & 7);
        float w = Whh[((size_t)dir * G4 + gb * Hn + uu) * Hn + k];
        sW2[k * 32 + r] = pk2(w, w);
    }
    for (int i = tid; i < 512; i += 256) sC[i] = 0.f;

    const int r  = tid & 31;            // gate row
    const int b0 = (tid >> 5) << 3;     // batch base (uniform per warp)
    const int xb = tid >> 2;            // xw staging: batch
    const int xgb = tid & 3;            //             gate block
    const int ck = tid >> 4;            // h staging: row in chunk
    const int cb = (tid & 15) << 2;     //            batch col (x4)
    const int pb = tid & 63;            // pointwise: batch
    const int pu = tid >> 6;            //            unit

    // ---- stage xw for step 0 into sX ----
    {
        int t0 = dir ? (Tn - 1) : 0;
        const float* xp = xw + (((size_t)dir * Tn + t0) * Bn + xb) * G4 + xgb * Hn + u0;
        float4 x0 = __ldg((const float4*)xp);
        float4 x1 = __ldg((const float4*)(xp + 4));
        float xv[8] = {x0.x, x0.y, x0.z, x0.w, x1.x, x1.y, x1.z, x1.w};
#pragma unroll
        for (int j = 0; j < 8; j++) sX[(xgb * 8 + j) * 68 + xb] = xv[j];
    }
    __syncthreads();

    unsigned* ctr = &g_barv[dir * 32];

#pragma unroll 1
    for (int s = 0; s < Tn; s++) {
        const int t = dir ? (Tn - 1 - s) : s;
        const float* hin = g_hT + (((size_t)(s & 1) * 2 + dir) << 15);

        // acc init from staged xw (read BEFORE any sync this step; sX rewritten at chunk 0 end)
        ulonglong2 x01 = *(const ulonglong2*)&sX[r * 68 + b0];
        ulonglong2 x23 = *(const ulonglong2*)&sX[r * 68 + b0 + 4];
        unsigned long long acc0 = x01.x, acc1 = x01.y, acc2 = x23.x, acc3 = x23.y;

        // prefetch next step's xw (independent of h)
        float4 xr0, xr1;
        if (s + 1 < Tn) {
            int tn = dir ? (Tn - 2 - s) : (s + 1);
            const float* xp = xw + (((size_t)dir * Tn + tn) * Bn + xb) * G4 + xgb * Hn + u0;
            xr0 = __ldg((const float4*)xp);
            xr1 = __ldg((const float4*)(xp + 4));
        }

        // pipeline prologue: load chunks 0,1; store chunk 0
        float4 pa[2], pbv[2];
        pa[0]  = __ldcg((const float4*)(hin + (size_t)(0  + ck) * Bn + cb));
        pbv[0] = __ldcg((const float4*)(hin + (size_t)(16 + ck) * Bn + cb));
        pa[1]  = __ldcg((const float4*)(hin + (size_t)(32 + ck) * Bn + cb));
        pbv[1] = __ldcg((const float4*)(hin + (size_t)(48 + ck) * Bn + cb));
        {
            float* b = sH;  // buf 0
            *(float4*)&b[ck * 72 + cb] = pa[0];
            *(float4*)&b[(ck + 16) * 72 + cb] = pbv[0];
        }
        __syncthreads();

#pragma unroll 1
        for (int i = 0; i < NCHUNK; i++) {
            // prefetch chunk i+2
            if (i + 2 < NCHUNK) {
                int kc2 = (i + 2) * 32;
                pa[i & 1]  = __ldcg((const float4*)(hin + (size_t)(kc2 + ck) * Bn + cb));
                pbv[i & 1] = __ldcg((const float4*)(hin + (size_t)(kc2 + 16 + ck) * Bn + cb));
            }
            // compute chunk i
            {
                const float* b = sH + (i % 3) * (32 * 72);
                const int kc = i * 32;
#pragma unroll 16
                for (int kk = 0; kk < 32; kk++) {
                    unsigned long long w2 = sW2[(kc + kk) * 32 + r];
                    ulonglong2 h01 = *(const ulonglong2*)&b[kk * 72 + b0];
                    ulonglong2 h23 = *(const ulonglong2*)&b[kk * 72 + b0 + 4];
                    fma2(acc0, h01.x, w2);
                    fma2(acc1, h01.y, w2);
                    fma2(acc2, h23.x, w2);
                    fma2(acc3, h23.y, w2);
                }
            }
            // store chunk i+1 (loaded earlier)
            if (i + 1 < NCHUNK) {
                float* b = sH + ((i + 1) % 3) * (32 * 72);
                *(float4*)&b[ck * 72 + cb] = pa[(i + 1) & 1];
                *(float4*)&b[(ck + 16) * 72 + cb] = pbv[(i + 1) & 1];
            }
            // stash next-step xw into sX (all threads read sX before chunk loop)
            if (i == 0 && s + 1 < Tn) {
                float xv[8] = {xr0.x, xr0.y, xr0.z, xr0.w, xr1.x, xr1.y, xr1.z, xr1.w};
#pragma unroll
                for (int j = 0; j < 8; j++) sX[(xgb * 8 + j) * 68 + xb] = xv[j];
            }
            __syncthreads();
        }

        // gate preacts -> sG
        {
            float2 p0 = upk2(acc0), p1 = upk2(acc1), p2 = upk2(acc2), p3 = upk2(acc3);
            sG[r*66+b0+0]=p0.x; sG[r*66+b0+1]=p0.y; sG[r*66+b0+2]=p1.x; sG[r*66+b0+3]=p1.y;
            sG[r*66+b0+4]=p2.x; sG[r*66+b0+5]=p2.y; sG[r*66+b0+6]=p3.x; sG[r*66+b0+7]=p3.y;
        }
        __syncthreads();

        // pointwise LSTM update
        float* hTout = g_hT + (((size_t)((s + 1) & 1) * 2 + dir) << 15);
#pragma unroll
        for (int hh = 0; hh < 2; hh++) {
            int ul = pu + hh * 4;
            float iv = sG[(0 * 8 + ul) * 66 + pb];
            float fv = sG[(1 * 8 + ul) * 66 + pb];
            float gv = sG[(2 * 8 + ul) * 66 + pb];
            float ov = sG[(3 * 8 + ul) * 66 + pb];
            iv = 1.f / (1.f + expf(-iv));
            fv = 1.f / (1.f + expf(-fv));
            gv = tanhf(gv);
            ov = 1.f / (1.f + expf(-ov));
            float c = fv * sC[ul * 64 + pb] + iv * gv;
            c = fminf(fmaxf(c, -100.f), 100.f);
            float hv = ov * tanhf(c);
            sC[ul * 64 + pb] = c;
            hTout[(size_t)(u0 + ul) * Bn + pb] = hv;
            out[((size_t)t * Bn + pb) * (2 * Hn) + dir * Hn + u0 + ul] = hv;
        }

        // per-direction grid barrier
        if (s < Tn - 1) {
            __syncthreads();
            if (tid == 0) {
                __threadfence();
                atomicAdd(ctr, 1u);
                unsigned target = 64u * (unsigned)(s + 1);
                while (*(volatile unsigned*)ctr < target) {}
                __threadfence();
            }
            __syncthreads();
        }
    }
}

// ============ attention logits + softmax (CTA per batch) ============
__global__ __launch_bounds__(512)
void attn_kernel(const float* __restrict__ h1, const float* __restrict__ Wa,
                 const float* __restrict__ ba, float* __restrict__ outp,
                 float* __restrict__ attn_sc) {
    __shared__ float sWa[Hn];
    __shared__ float red[Tn];
    const int b = blockIdx.x, t = threadIdx.x;
    sWa[t] = Wa[t];
    __syncthreads();

    const float* hp = h1 + ((size_t)t * Bn + b) * (2 * Hn);
    float acc = 0.f;
#pragma unroll 4
    for (int u = 0; u < Hn; u += 4) {
        float4 hf = *(const float4*)(hp + u);
        float4 hb = *(const float4*)(hp + Hn + u);
        float4 wv = *(const float4*)(sWa + u);
        acc += (hf.x + hb.x) * wv.x + (hf.y + hb.y) * wv.y +
               (hf.z + hb.z) * wv.z + (hf.w + hb.w) * wv.w;
    }
    float logit = acc + ba[0];

    red[t] = logit; __syncthreads();
    for (int st = 256; st > 0; st >>= 1) {
        if (t < st) red[t] = fmaxf(red[t], red[t + st]);
        __syncthreads();
    }
    float m = red[0]; __syncthreads();
    float e = expf(logit - m);
    red[t] = e; __syncthreads();
    for (int st = 256; st > 0; st >>= 1) {
        if (t < st) red[t] += red[t + st];
        __syncthreads();
    }
    float a = e / red[0];
    outp[Bn * NOUT + b * Tn + t] = a;
    attn_sc[b * Tn + t] = a;
}

// ============ attention pooling + head (CTA per batch) ============
__global__ __launch_bounds__(512)
void pool_kernel(const float* __restrict__ h1, const float* __restrict__ Wo,
                 const float* __restrict__ bo, const float* __restrict__ attn_sc,
                 float* __restrict__ outp) {
    __shared__ float sa[Tn];
    __shared__ float sp[Hn];
    const int b = blockIdx.x, u = threadIdx.x;
    sa[u] = attn_sc[b * Tn + u];
    __syncthreads();

    float p = 0.f;
#pragma unroll 1
    for (int t = 0; t < Tn; t++) {
        const float* hp = h1 + ((size_t)t * Bn + b) * (2 * Hn);
        p += (hp[u] + hp[Hn + u]) * sa[t];
    }
    sp[u] = p;
    __syncthreads();

    if (u < NOUT) {
        float s = bo[u];
        const float* wp = Wo + (size_t)u * Hn;
        for (int k = 0; k < Hn; k++) s += sp[k] * wp[k];
        outp[b * NOUT + u] = s;
    }
}

extern "C" void kernel_launch(void* const* d_in, const int* in_sizes, int n_in,
                              void* d_out, int out_size) {
    (void)in_sizes; (void)n_in; (void)out_size;
    const float* input = (const float*)d_in[0];
    const float* Wih0  = (const float*)d_in[1];
    const float* Whh0  = (const float*)d_in[2];
    const float* b0    = (const float*)d_in[3];
    const float* Wih1  = (const float*)d_in[4];
    const float* Whh1  = (const float*)d_in[5];
    const float* b1    = (const float*)d_in[6];
    const float* Wa    = (const float*)d_in[7];
    const float* ba    = (const float*)d_in[8];
    const float* Wo    = (const float*)d_in[9];
    const float* bo    = (const float*)d_in[10];
    float* outp = (float*)d_out;

    float *xw, *out0, *out1, *attn_sc;
    cudaGetSymbolAddress((void**)&xw, g_xw);
    cudaGetSymbolAddress((void**)&out0, g_out0);
    cudaGetSymbolAddress((void**)&out1, g_out1);
    cudaGetSymbolAddress((void**)&attn_sc, g_attn);

    cudaFuncSetAttribute(lstm_kernel, cudaFuncAttributeMaxDynamicSharedMemorySize,
                         LSTM_SMEM_BYTES);

    dim3 ggrid(G4 / GBN, (Tn * Bn) / GBM, 2);

    // layer 0
    gemm_xw_kernel<<<ggrid, 256>>>(input, Wih0, b0, xw, 256);
    init_kernel<<<64, 256>>>();
    lstm_kernel<<<NCTA_LSTM, 256, LSTM_SMEM_BYTES>>>(xw, Whh0, out0);

    // layer 1
    gemm_xw_kernel<<<ggrid, 256>>>(out0, Wih1, b1, xw, 1024);
    init_kernel<<<64, 256>>>();
    lstm_kernel<<<NCTA_LSTM, 256, LSTM_SMEM_BYTES>>>(xw, Whh1, out1);

    // attention + head
    attn_kernel<<<Bn, Tn>>>(out1, Wa, ba, outp, attn_sc);
    pool_kernel<<<Bn, Tn>>>(out1, Wo, bo, attn_sc, outp);
}

// round 5
// speedup vs baseline: 1.3215x; 1.3215x over previous
#include <cuda_runtime.h>
#include <math.h>

#define Tn   512
#define Bn   64
#define Hn   512
#define G4   2048
#define NOUT 128
#define Mtot (Tn * Bn)          // 32768
#define NCTA_LSTM 128
#define NCHUNK 8                // 512 / 64

// ---------------- scratch ----------------
__device__ float g_xw[(size_t)2 * G4 * Mtot];        // xw_T[dir][n][m]
__device__ float g_out0[(size_t)2 * Hn * Mtot];      // out0_T[dir][u][m]
__device__ float g_out1[(size_t)2 * Hn * Mtot];      // out1_T[dir][u][m]
__device__ float g_hT[2 * 2 * Hn * Bn];              // [buf][dir][u][b]
__device__ float g_logit[Tn * Bn];                   // [t][b]
__device__ float g_attnT[Tn * Bn];                   // [t][b]
__device__ float g_pooledT[Hn * Bn];                 // [u][b]
__device__ unsigned g_barv[64];                      // per-dir counters (dir*32)

__device__ __forceinline__ unsigned long long pk2(float lo, float hi) {
    unsigned long long r;
    asm("mov.b64 %0, {%1, %2};" : "=l"(r) : "f"(lo), "f"(hi));
    return r;
}
__device__ __forceinline__ void fma2(unsigned long long& d, unsigned long long a, unsigned long long b) {
    asm("fma.rn.f32x2 %0, %1, %2, %0;" : "+l"(d) : "l"(a), "l"(b));
}
__device__ __forceinline__ float2 upk2(unsigned long long v) {
    float2 r;
    asm("mov.b64 {%0, %1}, %2;" : "=f"(r.x), "=f"(r.y) : "l"(v));
    return r;
}
__device__ __forceinline__ unsigned ldacq(const unsigned* p) {
    unsigned v;
    asm volatile("ld.acquire.gpu.global.b32 %0, [%1];" : "=r"(v) : "l"(p) : "memory");
    return v;
}

// ===================== GEMM =====================
// C_T[dir][n][m] = sum_k X(m,k) * W[dir][n][k] + b[dir][n]
// XT=0: X row-major [M][K];  XT=1: X transposed [K][M]
#define GBM 128
#define GBN 128
#define GBK 16

template <int XT>
__global__ __launch_bounds__(256, 2)
void gemm_xw_kernel(const float* __restrict__ X, const float* __restrict__ W,
                    const float* __restrict__ bias, float* __restrict__ C, int K) {
    const int N = G4, M = Mtot;
    const int dir = blockIdx.z;
    const float* Wd = W + (size_t)dir * N * K;
    const float* bd = bias + (size_t)dir * N;
    float* Cd = C + (size_t)dir * (size_t)N * M;

    __shared__ __align__(16) float As[GBK][GBM + 4];
    __shared__ __align__(16) float Bs[GBK][GBN + 4];

    const int tid = threadIdx.x;
    const int m0 = blockIdx.y * GBM;
    const int n0 = blockIdx.x * GBN;
    const int tx = tid & 15, ty = tid >> 4;
    const int lrow = tid >> 1;
    const int lk = (tid & 1) * 8;
    // XT=1 staging indices
    const int skk = tid >> 4;          // k row 0..15
    const int sc4 = (tid & 15) * 4;    // m col

    unsigned long long acc[8][4];
#pragma unroll
    for (int i = 0; i < 8; i++)
#pragma unroll
        for (int j = 0; j < 4; j++) acc[i][j] = 0ULL;

#pragma unroll 1
    for (int kt = 0; kt < K; kt += GBK) {
        float4 b0 = *(const float4*)(Wd + (size_t)(n0 + lrow) * K + kt + lk);
        float4 b1 = *(const float4*)(Wd + (size_t)(n0 + lrow) * K + kt + lk + 4);
        if (XT == 0) {
            float4 a0 = *(const float4*)(X + (size_t)(m0 + lrow) * K + kt + lk);
            float4 a1 = *(const float4*)(X + (size_t)(m0 + lrow) * K + kt + lk + 4);
            __syncthreads();
            As[lk+0][lrow]=a0.x; As[lk+1][lrow]=a0.y; As[lk+2][lrow]=a0.z; As[lk+3][lrow]=a0.w;
            As[lk+4][lrow]=a1.x; As[lk+5][lrow]=a1.y; As[lk+6][lrow]=a1.z; As[lk+7][lrow]=a1.w;
        } else {
            float4 a0 = *(const float4*)(X + (size_t)(kt + skk) * M + m0 + sc4);
            float4 a1 = *(const float4*)(X + (size_t)(kt + skk) * M + m0 + sc4 + 64);
            __syncthreads();
            *(float4*)&As[skk][sc4] = a0;
            *(float4*)&As[skk][sc4 + 64] = a1;
        }
        Bs[lk+0][lrow]=b0.x; Bs[lk+1][lrow]=b0.y; Bs[lk+2][lrow]=b0.z; Bs[lk+3][lrow]=b0.w;
        Bs[lk+4][lrow]=b1.x; Bs[lk+5][lrow]=b1.y; Bs[lk+6][lrow]=b1.z; Bs[lk+7][lrow]=b1.w;
        __syncthreads();
#pragma unroll
        for (int k = 0; k < GBK; k++) {
            float4 af0 = *(const float4*)&As[k][ty * 8];
            float4 af1 = *(const float4*)&As[k][ty * 8 + 4];
            ulonglong2 bp0 = *(const ulonglong2*)&Bs[k][tx * 8];
            ulonglong2 bp1 = *(const ulonglong2*)&Bs[k][tx * 8 + 4];
            float a[8] = {af0.x, af0.y, af0.z, af0.w, af1.x, af1.y, af1.z, af1.w};
            unsigned long long b2[4] = {bp0.x, bp0.y, bp1.x, bp1.y};
#pragma unroll
            for (int i = 0; i < 8; i++) {
                unsigned long long ad = pk2(a[i], a[i]);
                fma2(acc[i][0], ad, b2[0]);
                fma2(acc[i][1], ad, b2[1]);
                fma2(acc[i][2], ad, b2[2]);
                fma2(acc[i][3], ad, b2[3]);
            }
        }
    }
    // transposed epilogue: for each of this thread's 8 n values, store 8 m floats
#pragma unroll
    for (int nn = 0; nn < 8; nn++) {
        const int j = nn >> 1;
        float v[8];
#pragma unroll
        for (int i = 0; i < 8; i++) {
            float2 p = upk2(acc[i][j]);
            v[i] = (nn & 1) ? p.y : p.x;
        }
        int n = n0 + tx * 8 + nn;
        float bv = bd[n];
#pragma unroll
        for (int i = 0; i < 8; i++) v[i] += bv;
        float* cp = Cd + (size_t)n * M + m0 + ty * 8;
        *(float4*)cp = make_float4(v[0], v[1], v[2], v[3]);
        *(float4*)(cp + 4) = make_float4(v[4], v[5], v[6], v[7]);
    }
}

// ===================== init =====================
__global__ void init_kernel() {
    int i = blockIdx.x * blockDim.x + threadIdx.x;
    if (i < 64) g_barv[i] = 0u;
    for (int j = i; j < 2 * 2 * Hn * Bn; j += gridDim.x * blockDim.x) g_hT[j] = 0.f;
}

// ===================== persistent LSTM layer =====================
// smem: sW [512][33] fp32 weights (k-major), sH 2x[64][72] h chunks,
//       sX [32][72] staged xw, sG [32][66] preacts, sC [512] cell
#define SW_PITCH 33
#define SH_PITCH 72
#define SMF_W  (512 * SW_PITCH)
#define SMF_H  (2 * 64 * SH_PITCH)
#define SMF_X  (32 * SH_PITCH)
#define SMF_G  (32 * 66)
#define SMF_C  512
#define LSTM_SMEM_BYTES ((SMF_W + SMF_H + SMF_X + SMF_G + SMF_C) * 4)

__global__ __launch_bounds__(256)
void lstm_kernel(const float* __restrict__ xwT, const float* __restrict__ Whh,
                 float* __restrict__ outT) {
    extern __shared__ float sm[];
    float* sW = sm;                      // [k][r]
    float* sH = sm + SMF_W;              // 2 bufs [64][72]
    float* sX = sH + SMF_H;              // [32][72]
    float* sG = sX + SMF_X;              // [32][66]
    float* sC = sG + SMF_G;              // [8][64]

    const int tid = threadIdx.x;
    const int dir = blockIdx.x >> 6;
    const int u0 = (blockIdx.x & 63) << 3;

    // load Whh slice, k-contiguous reads, [k][r] smem layout
    for (int i = tid; i < 32 * 512; i += 256) {
        int rr = i >> 9, k = i & 511;
        float w = Whh[((size_t)dir * G4 + (rr >> 3) * Hn + u0 + (rr & 7)) * Hn + k];
        sW[k * SW_PITCH + rr] = w;
    }
    for (int i = tid; i < 512; i += 256) sC[i] = 0.f;

    const int r  = tid & 31;             // gate row within CTA
    const int b0 = (tid >> 5) << 3;      // batch base per warp
    const int xr = tid >> 3;             // xw staging row 0..31
    const int xc = (tid & 7) * 8;        // xw staging col
    const int hr16 = tid >> 4;           // h staging row-within-16
    const int hc = (tid & 15) * 4;       // h staging col (x4)
    const int pb = tid & 63;             // pointwise batch
    const int pu = tid >> 6;             // pointwise unit 0..3

    // stage xw for step 0
    {
        int t0 = dir ? (Tn - 1) : 0;
        const float* xp = xwT + ((size_t)dir * G4 + (xr >> 3) * Hn + u0 + (xr & 7)) * Mtot
                              + (size_t)t0 * Bn + xc;
        float4 x0 = __ldg((const float4*)xp);
        float4 x1 = __ldg((const float4*)(xp + 4));
        *(float4*)&sX[xr * SH_PITCH + xc] = x0;
        *(float4*)&sX[xr * SH_PITCH + xc + 4] = x1;
    }
    __syncthreads();

    unsigned* ctr = &g_barv[dir * 32];

#pragma unroll 1
    for (int s = 0; s < Tn; s++) {
        const int t = dir ? (Tn - 1 - s) : s;
        const float* hin = g_hT + (((size_t)(s & 1) * 2 + dir) << 15);

        // acc from staged xw
        ulonglong2 x01 = *(const ulonglong2*)&sX[r * SH_PITCH + b0];
        ulonglong2 x23 = *(const ulonglong2*)&sX[r * SH_PITCH + b0 + 4];
        unsigned long long acc0 = x01.x, acc1 = x01.y, acc2 = x23.x, acc3 = x23.y;

        // prefetch next step's xw (coalesced)
        float4 xf0, xf1;
        if (s + 1 < Tn) {
            int tnx = dir ? (Tn - 2 - s) : (s + 1);
            const float* xp = xwT + ((size_t)dir * G4 + (xr >> 3) * Hn + u0 + (xr & 7)) * Mtot
                                  + (size_t)tnx * Bn + xc;
            xf0 = __ldg((const float4*)xp);
            xf1 = __ldg((const float4*)(xp + 4));
        }

        // prologue: load + store chunk 0
        {
            float4 c0 = __ldcg((const float4*)(hin + (size_t)(0 * 16 + hr16) * Bn + hc));
            float4 c1 = __ldcg((const float4*)(hin + (size_t)(1 * 16 + hr16) * Bn + hc));
            float4 c2 = __ldcg((const float4*)(hin + (size_t)(2 * 16 + hr16) * Bn + hc));
            float4 c3 = __ldcg((const float4*)(hin + (size_t)(3 * 16 + hr16) * Bn + hc));
            *(float4*)&sH[(0 * 16 + hr16) * SH_PITCH + hc] = c0;
            *(float4*)&sH[(1 * 16 + hr16) * SH_PITCH + hc] = c1;
            *(float4*)&sH[(2 * 16 + hr16) * SH_PITCH + hc] = c2;
            *(float4*)&sH[(3 * 16 + hr16) * SH_PITCH + hc] = c3;
        }
        __syncthreads();

#pragma unroll 2
        for (int i = 0; i < NCHUNK; i++) {
            // prefetch chunk i+1 into regs
            float4 n0q, n1q, n2q, n3q;
            if (i + 1 < NCHUNK) {
                const float* hp = hin + (size_t)(i + 1) * 64 * Bn;
                n0q = __ldcg((const float4*)(hp + (size_t)(0 * 16 + hr16) * Bn + hc));
                n1q = __ldcg((const float4*)(hp + (size_t)(1 * 16 + hr16) * Bn + hc));
                n2q = __ldcg((const float4*)(hp + (size_t)(2 * 16 + hr16) * Bn + hc));
                n3q = __ldcg((const float4*)(hp + (size_t)(3 * 16 + hr16) * Bn + hc));
            }
            // compute chunk i
            {
                const float* buf = sH + (i & 1) * (64 * SH_PITCH);
                const float* wp = sW + (i * 64) * SW_PITCH;
#pragma unroll 16
                for (int kk = 0; kk < 64; kk++) {
                    float w = wp[kk * SW_PITCH + r];
                    unsigned long long w2 = pk2(w, w);
                    ulonglong2 h01 = *(const ulonglong2*)&buf[kk * SH_PITCH + b0];
                    ulonglong2 h23 = *(const ulonglong2*)&buf[kk * SH_PITCH + b0 + 4];
                    fma2(acc0, h01.x, w2);
                    fma2(acc1, h01.y, w2);
                    fma2(acc2, h23.x, w2);
                    fma2(acc3, h23.y, w2);
                }
            }
            // store chunk i+1
            if (i + 1 < NCHUNK) {
                float* buf = sH + ((i + 1) & 1) * (64 * SH_PITCH);
                *(float4*)&buf[(0 * 16 + hr16) * SH_PITCH + hc] = n0q;
                *(float4*)&buf[(1 * 16 + hr16) * SH_PITCH + hc] = n1q;
                *(float4*)&buf[(2 * 16 + hr16) * SH_PITCH + hc] = n2q;
                *(float4*)&buf[(3 * 16 + hr16) * SH_PITCH + hc] = n3q;
            }
            // stash next-step xw once (after all top-reads of sX: first sync passed)
            if (i == 0 && s + 1 < Tn) {
                *(float4*)&sX[xr * SH_PITCH + xc] = xf0;
                *(float4*)&sX[xr * SH_PITCH + xc + 4] = xf1;
            }
            __syncthreads();
        }

        // preacts -> sG
        {
            float2 p0 = upk2(acc0), p1 = upk2(acc1), p2 = upk2(acc2), p3 = upk2(acc3);
            sG[r*66+b0+0]=p0.x; sG[r*66+b0+1]=p0.y; sG[r*66+b0+2]=p1.x; sG[r*66+b0+3]=p1.y;
            sG[r*66+b0+4]=p2.x; sG[r*66+b0+5]=p2.y; sG[r*66+b0+6]=p3.x; sG[r*66+b0+7]=p3.y;
        }
        __syncthreads();

        // pointwise update (2 cells per thread), coalesced transposed writes
        float* hTout = g_hT + (((size_t)((s + 1) & 1) * 2 + dir) << 15);
#pragma unroll
        for (int hh = 0; hh < 2; hh++) {
            int ul = pu + hh * 4;
            float iv = sG[(0 * 8 + ul) * 66 + pb];
            float fv = sG[(1 * 8 + ul) * 66 + pb];
            float gv = sG[(2 * 8 + ul) * 66 + pb];
            float ov = sG[(3 * 8 + ul) * 66 + pb];
            iv = 1.f / (1.f + expf(-iv));
            fv = 1.f / (1.f + expf(-fv));
            gv = tanhf(gv);
            ov = 1.f / (1.f + expf(-ov));
            float c = fv * sC[ul * 64 + pb] + iv * gv;
            c = fminf(fmaxf(c, -100.f), 100.f);
            float hv = ov * tanhf(c);
            sC[ul * 64 + pb] = c;
            hTout[(size_t)(u0 + ul) * Bn + pb] = hv;
            outT[((size_t)dir * Hn + u0 + ul) * Mtot + (size_t)t * Bn + pb] = hv;
        }

        // grid barrier (per direction)
        if (s < Tn - 1) {
            __threadfence();
            __syncthreads();
            if (tid == 0) atomicAdd(ctr, 1u);
            unsigned target = 64u * (unsigned)(s + 1);
            while (ldacq(ctr) < target) {}
        }
    }
}

// ===================== attention logits =====================
// grid = Tn (t), 512 threads: ug = tid>>6 (u chunk), b = tid&63
__global__ __launch_bounds__(512)
void attn_logit_kernel(const float* __restrict__ h1T, const float* __restrict__ Wa,
                       const float* __restrict__ ba, float* __restrict__ logit) {
    __shared__ float sWa[Hn];
    __shared__ float red[8][64];
    const int t = blockIdx.x;
    const int ug = threadIdx.x >> 6, b = threadIdx.x & 63;
    sWa[threadIdx.x] = Wa[threadIdx.x];
    __syncthreads();

    float acc = 0.f;
    const size_t moff = (size_t)t * Bn + b;
#pragma unroll 4
    for (int uu = 0; uu < 64; uu++) {
        int u = ug * 64 + uu;
        float hf = h1T[(size_t)u * Mtot + moff];
        float hb = h1T[((size_t)Hn + u) * Mtot + moff];
        acc += (hf + hb) * sWa[u];
    }
    red[ug][b] = acc;
    __syncthreads();
    if (ug == 0) {
        float s = ba[0];
#pragma unroll
        for (int g = 0; g < 8; g++) s += red[g][b];
        logit[t * Bn + b] = s;
    }
}

// ===================== softmax over t (CTA per b) =====================
__global__ __launch_bounds__(512)
void softmax_kernel(const float* __restrict__ logit, float* __restrict__ outp,
                    float* __restrict__ aT) {
    __shared__ float red[Tn];
    const int b = blockIdx.x, t = threadIdx.x;
    float v = logit[t * Bn + b];
    red[t] = v; __syncthreads();
    for (int st = 256; st > 0; st >>= 1) {
        if (t < st) red[t] = fmaxf(red[t], red[t + st]);
        __syncthreads();
    }
    float m = red[0]; __syncthreads();
    float e = expf(v - m);
    red[t] = e; __syncthreads();
    for (int st = 256; st > 0; st >>= 1) {
        if (t < st) red[t] += red[t + st];
        __syncthreads();
    }
    float a = e / red[0];
    outp[Bn * NOUT + b * Tn + t] = a;
    aT[t * Bn + b] = a;
}

// ===================== attention pooling (CTA per u) =====================
__global__ __launch_bounds__(64)
void pool_kernel(const float* __restrict__ h1T, const float* __restrict__ aT,
                 float* __restrict__ pooledT) {
    const int u = blockIdx.x, b = threadIdx.x;
    const float* hf = h1T + (size_t)u * Mtot;
    const float* hb = h1T + ((size_t)Hn + u) * Mtot;
    float acc = 0.f;
#pragma unroll 4
    for (int t = 0; t < Tn; t++) {
        acc += (hf[t * Bn + b] + hb[t * Bn + b]) * aT[t * Bn + b];
    }
    pooledT[u * Bn + b] = acc;
}

// ===================== output head (CTA per b) =====================
__global__ __launch_bounds__(128)
void pred_kernel(const float* __restrict__ pooledT, const float* __restrict__ Wo,
                 const float* __restrict__ bo, float* __restrict__ outp) {
    __shared__ float sp[Hn];
    const int b = blockIdx.x, o = threadIdx.x;
    for (int u = o; u < Hn; u += 128) sp[u] = pooledT[u * Bn + b];
    __syncthreads();
    float s = bo[o];
    const float* wp = Wo + (size_t)o * Hn;
#pragma unroll 4
    for (int u = 0; u < Hn; u++) s += sp[u] * wp[u];
    outp[b * NOUT + o] = s;
}

// ===================== launch =====================
extern "C" void kernel_launch(void* const* d_in, const int* in_sizes, int n_in,
                              void* d_out, int out_size) {
    (void)in_sizes; (void)n_in; (void)out_size;
    const float* input = (const float*)d_in[0];
    const float* Wih0  = (const float*)d_in[1];
    const float* Whh0  = (const float*)d_in[2];
    const float* b0    = (const float*)d_in[3];
    const float* Wih1  = (const float*)d_in[4];
    const float* Whh1  = (const float*)d_in[5];
    const float* b1    = (const float*)d_in[6];
    const float* Wa    = (const float*)d_in[7];
    const float* ba    = (const float*)d_in[8];
    const float* Wo    = (const float*)d_in[9];
    const float* bo    = (const float*)d_in[10];
    float* outp = (float*)d_out;

    float *xw, *out0, *out1, *logit, *aT, *pooledT;
    cudaGetSymbolAddress((void**)&xw, g_xw);
    cudaGetSymbolAddress((void**)&out0, g_out0);
    cudaGetSymbolAddress((void**)&out1, g_out1);
    cudaGetSymbolAddress((void**)&logit, g_logit);
    cudaGetSymbolAddress((void**)&aT, g_attnT);
    cudaGetSymbolAddress((void**)&pooledT, g_pooledT);

    cudaFuncSetAttribute(lstm_kernel, cudaFuncAttributeMaxDynamicSharedMemorySize,
                         LSTM_SMEM_BYTES);

    dim3 ggrid(G4 / GBN, Mtot / GBM, 2);

    // layer 0
    gemm_xw_kernel<0><<<ggrid, 256>>>(input, Wih0, b0, xw, 256);
    init_kernel<<<64, 256>>>();
    lstm_kernel<<<NCTA_LSTM, 256, LSTM_SMEM_BYTES>>>(xw, Whh0, out0);

    // layer 1
    gemm_xw_kernel<1><<<ggrid, 256>>>(out0, Wih1, b1, xw, 1024);
    init_kernel<<<64, 256>>>();
    lstm_kernel<<<NCTA_LSTM, 256, LSTM_SMEM_BYTES>>>(xw, Whh1, out1);

    // attention + head
    attn_logit_kernel<<<Tn, 512>>>(out1, Wa, ba, logit);
    softmax_kernel<<<Bn, Tn>>>(logit, outp, aT);
    pool_kernel<<<Hn, Bn>>>(out1, aT, pooledT);
    pred_kernel<<<Bn, NOUT>>>(pooledT, Wo, bo, outp);
}

// round 8
// speedup vs baseline: 1.6193x; 1.2253x over previous
#include <cuda_runtime.h>
#include <cuda_bf16.h>
#include <cstdint>
#include <math.h>

#define Tn   512
#define Bn   64
#define Hn   512
#define G4   2048
#define NOUT 128
#define Mtot (Tn * Bn)          // 32768
#define NCTA_LSTM 128
#define NCHUNK 8                // 512 / 64 (lstm)

// ---------------- scratch ----------------
__device__ float g_xw[(size_t)2 * G4 * Mtot];        // xw_T[dir][n][m]
__device__ float g_out0[(size_t)2 * Hn * Mtot];      // out0_T[dir][u][m]
__device__ float g_out1[(size_t)2 * Hn * Mtot];      // out1_T[dir][u][m]
__device__ float g_hT[2 * 2 * Hn * Bn];              // [buf][dir][u][b]
__device__ float g_logit[Tn * Bn];
__device__ float g_attnT[Tn * Bn];
__device__ float g_pooledT[Hn * Bn];
__device__ unsigned g_barv[64];
// bf16 split buffers
__device__ __nv_bfloat16 g_xhi[(size_t)Mtot * 1024];
__device__ __nv_bfloat16 g_xlo[(size_t)Mtot * 1024];
__device__ __nv_bfloat16 g_whi[2 * G4 * 1024];
__device__ __nv_bfloat16 g_wlo[2 * G4 * 1024];

__device__ __forceinline__ unsigned long long pk2(float lo, float hi) {
    unsigned long long r;
    asm("mov.b64 %0, {%1, %2};" : "=l"(r) : "f"(lo), "f"(hi));
    return r;
}
__device__ __forceinline__ void fma2(unsigned long long& d, unsigned long long a, unsigned long long b) {
    asm("fma.rn.f32x2 %0, %1, %2, %0;" : "+l"(d) : "l"(a), "l"(b));
}
__device__ __forceinline__ float2 upk2(unsigned long long v) {
    float2 r;
    asm("mov.b64 {%0, %1}, %2;" : "=f"(r.x), "=f"(r.y) : "l"(v));
    return r;
}
__device__ __forceinline__ unsigned ldacq(const unsigned* p) {
    unsigned v;
    asm volatile("ld.acquire.gpu.global.b32 %0, [%1];" : "=r"(v) : "l"(p) : "memory");
    return v;
}

// ==================== mma.sync helpers (sm_80+ PTX, safe on sm_103) ====================
__device__ __forceinline__ unsigned smem_u32(const void* p) {
    unsigned a;
    asm("{ .reg .u64 t; cvta.to.shared.u64 t, %1; cvt.u32.u64 %0, t; }" : "=r"(a) : "l"(p));
    return a;
}
__device__ __forceinline__ void ldsm4(unsigned& r0, unsigned& r1, unsigned& r2, unsigned& r3,
                                      unsigned addr) {
    asm volatile("ldmatrix.sync.aligned.m8n8.x4.shared.b16 {%0,%1,%2,%3}, [%4];"
                 : "=r"(r0), "=r"(r1), "=r"(r2), "=r"(r3) : "r"(addr));
}
__device__ __forceinline__ void mma16816(float* c, const unsigned* a, unsigned b0, unsigned b1) {
    asm volatile(
        "mma.sync.aligned.m16n8k16.row.col.f32.bf16.bf16.f32 "
        "{%0,%1,%2,%3}, {%4,%5,%6,%7}, {%8,%9}, {%0,%1,%2,%3};"
        : "+f"(c[0]), "+f"(c[1]), "+f"(c[2]), "+f"(c[3])
        : "r"(a[0]), "r"(a[1]), "r"(a[2]), "r"(a[3]), "r"(b0), "r"(b1));
}
__device__ __forceinline__ void cpasync16(unsigned dst, const void* src) {
    asm volatile("cp.async.cg.shared.global [%0], [%1], 16;" :: "r"(dst), "l"(src));
}
__device__ __forceinline__ void cpasync_commit() {
    asm volatile("cp.async.commit_group;" ::: "memory");
}
__device__ __forceinline__ void cpasync_wait0() {
    asm volatile("cp.async.wait_group 0;" ::: "memory");
}

// ==================== fp32 -> bf16 hi/lo converters ====================
__global__ void convert_split_kernel(const float* __restrict__ in,
                                     __nv_bfloat16* __restrict__ hi,
                                     __nv_bfloat16* __restrict__ lo, int n) {
    int i = blockIdx.x * blockDim.x + threadIdx.x;
    for (; i < n; i += gridDim.x * blockDim.x) {
        float v = in[i];
        __nv_bfloat16 h = __float2bfloat16_rn(v);
        hi[i] = h;
        lo[i] = __float2bfloat16_rn(v - __bfloat162float(h));
    }
}

// transpose-convert: in[k][m] fp32 (k=1024, m=32768) -> hi/lo[m][k]
__global__ __launch_bounds__(256)
void transpose_split_kernel(const float* __restrict__ in,
                            __nv_bfloat16* __restrict__ hi,
                            __nv_bfloat16* __restrict__ lo) {
    __shared__ float s[32][33];
    const int m0 = blockIdx.x * 32, k0 = blockIdx.y * 32;
    const int tx = threadIdx.x, ty = threadIdx.y;  // 32 x 8
#pragma unroll
    for (int j = 0; j < 4; j++)
        s[ty + 8 * j][tx] = in[(size_t)(k0 + ty + 8 * j) * Mtot + m0 + tx];
    __syncthreads();
#pragma unroll
    for (int j = 0; j < 4; j++) {
        float v = s[tx][ty + 8 * j];
        __nv_bfloat16 h = __float2bfloat16_rn(v);
        size_t o = (size_t)(m0 + ty + 8 * j) * 1024 + k0 + tx;
        hi[o] = h;
        lo[o] = __float2bfloat16_rn(v - __bfloat162float(h));
    }
}

// ==================== mma.sync GEMM ====================
// C[n][m] = sum_k (Whi+Wlo)[n][k] * (Xhi+Xlo)[m][k] + bias[n]   (lo*lo dropped)
// n flattened over [2*G4] (dir folded). CTA tile 128n x 128m, K chunks of 64,
// double-buffered smem, cp.async staging.
#define GP      72                      // smem row pitch in bf16 (144 B)
#define GTILE   (128 * GP * 2)          // one 128x64 bf16 tile, bytes (18432)
#define GBUF    (4 * GTILE)             // Whi,Wlo,Xhi,Xlo         (73728)
#define GEMM_SMEM (2 * GBUF)            // double buffer           (147456)

__global__ __launch_bounds__(256, 1)
void mma_gemm_kernel(const __nv_bfloat16* __restrict__ Whi, const __nv_bfloat16* __restrict__ Wlo,
                     const __nv_bfloat16* __restrict__ Xhi, const __nv_bfloat16* __restrict__ Xlo,
                     const float* __restrict__ bias, float* __restrict__ C, int K) {
    extern __shared__ char smem[];
    const unsigned sb = smem_u32(smem);
    const int tid = threadIdx.x;
    const int wid = tid >> 5, lane = tid & 31;
    const int wa = wid & 3;              // warp n-slot (4 x 32 rows)
    const int wb = wid >> 2;             // warp m-slot (2 x 64 cols)
    const int n0 = blockIdx.x * 128;     // over flattened 4096 n-rows
    const int m0 = blockIdx.y * 128;
    const int NC = K >> 6;

    const __nv_bfloat16* gsrc[4] = {Whi + (size_t)n0 * K, Wlo + (size_t)n0 * K,
                                    Xhi + (size_t)m0 * K, Xlo + (size_t)m0 * K};

    float acc[2][8][4];
#pragma unroll
    for (int i = 0; i < 2; i++)
#pragma unroll
        for (int j = 0; j < 8; j++)
#pragma unroll
            for (int q = 0; q < 4; q++) acc[i][j][q] = 0.f;

    // stage chunk 0 into buffer 0
#pragma unroll
    for (int tgt = 0; tgt < 4; tgt++) {
#pragma unroll
        for (int i = 0; i < 4; i++) {
            int lin = tid + i * 256;
            int row = lin >> 3, unit = lin & 7;
            cpasync16(sb + tgt * GTILE + (row * GP + unit * 8) * 2,
                      gsrc[tgt] + (size_t)row * K + unit * 8);
        }
    }
    cpasync_commit();

    // ldmatrix lane addressing
    const int a_roff = (lane & 7) + ((lane >> 3) & 1) * 8;
    const int a_koff = ((lane >> 4) & 1) * 8;
    const int b_roff = (lane & 7) + ((lane >> 4) & 1) * 8;   // seg>>1
    const int b_koff = ((lane >> 3) & 1) * 8;                // seg&1

#pragma unroll 1
    for (int c = 0; c < NC; c++) {
        cpasync_wait0();
        __syncthreads();
        // prefetch next chunk into other buffer
        if (c + 1 < NC) {
            const int kc = (c + 1) * 64;
            const unsigned bo = ((c + 1) & 1) * GBUF;
#pragma unroll
            for (int tgt = 0; tgt < 4; tgt++) {
#pragma unroll
                for (int i = 0; i < 4; i++) {
                    int lin = tid + i * 256;
                    int row = lin >> 3, unit = lin & 7;
                    cpasync16(sb + bo + tgt * GTILE + (row * GP + unit * 8) * 2,
                              gsrc[tgt] + (size_t)row * K + kc + unit * 8);
                }
            }
            cpasync_commit();
        }
        // compute on buffer c&1
        const unsigned cb = (c & 1) * GBUF;
#pragma unroll
        for (int ks = 0; ks < 4; ks++) {
            const int k0 = ks * 16;
            unsigned ahi[2][4], alo[2][4], bhi[4][4], blo[4][4];
#pragma unroll
            for (int mf = 0; mf < 2; mf++) {
                int row = wa * 32 + mf * 16 + a_roff;
                unsigned ad = sb + cb + (row * GP + k0 + a_koff) * 2;
                ldsm4(ahi[mf][0], ahi[mf][1], ahi[mf][2], ahi[mf][3], ad);
                ldsm4(alo[mf][0], alo[mf][1], alo[mf][2], alo[mf][3], ad + GTILE);
            }
#pragma unroll
            for (int nf = 0; nf < 4; nf++) {
                int row = wb * 64 + nf * 16 + b_roff;
                unsigned ad = sb + cb + 2 * GTILE + (row * GP + k0 + b_koff) * 2;
                ldsm4(bhi[nf][0], bhi[nf][1], bhi[nf][2], bhi[nf][3], ad);
                ldsm4(blo[nf][0], blo[nf][1], blo[nf][2], blo[nf][3], ad + GTILE);
            }
#pragma unroll
            for (int mf = 0; mf < 2; mf++)
#pragma unroll
                for (int nf = 0; nf < 4; nf++)
#pragma unroll
                    for (int hf = 0; hf < 2; hf++) {
                        float* cc = acc[mf][nf * 2 + hf];
                        mma16816(cc, ahi[mf], bhi[nf][hf * 2], bhi[nf][hf * 2 + 1]);
                        mma16816(cc, ahi[mf], blo[nf][hf * 2], blo[nf][hf * 2 + 1]);
                        mma16816(cc, alo[mf], bhi[nf][hf * 2], bhi[nf][hf * 2 + 1]);
                    }
        }
        __syncthreads();
    }

    // epilogue: direct stores, bias added
    const int g = lane >> 2, tig = lane & 3;
#pragma unroll
    for (int mf = 0; mf < 2; mf++) {
        const int nr = n0 + wa * 32 + mf * 16 + g;
        const float bv0 = bias[nr];
        const float bv1 = bias[nr + 8];
#pragma unroll
        for (int j = 0; j < 8; j++) {
            const int mcol = m0 + wb * 64 + j * 8 + tig * 2;
            float2 v0 = make_float2(acc[mf][j][0] + bv0, acc[mf][j][1] + bv0);
            float2 v1 = make_float2(acc[mf][j][2] + bv1, acc[mf][j][3] + bv1);
            *(float2*)&C[(size_t)nr * Mtot + mcol] = v0;
            *(float2*)&C[(size_t)(nr + 8) * Mtot + mcol] = v1;
        }
    }
}

// ===================== init =====================
__global__ void init_kernel() {
    int i = blockIdx.x * blockDim.x + threadIdx.x;
    if (i < 64) g_barv[i] = 0u;
    for (int j = i; j < 2 * 2 * Hn * Bn; j += gridDim.x * blockDim.x) g_hT[j] = 0.f;
}

// ===================== persistent LSTM layer =====================
#define SW_PITCH 33
#define SH_PITCH 72
#define SMF_W  (512 * SW_PITCH)
#define SMF_H  (2 * 64 * SH_PITCH)
#define SMF_X  (32 * SH_PITCH)
#define SMF_G  (32 * 66)
#define SMF_C  512
#define LSTM_SMEM_BYTES ((SMF_W + SMF_H + SMF_X + SMF_G + SMF_C) * 4)

__global__ __launch_bounds__(256)
void lstm_kernel(const float* __restrict__ xwT, const float* __restrict__ Whh,
                 float* __restrict__ outT) {
    extern __shared__ float sm[];
    float* sW = sm;
    float* sH = sm + SMF_W;
    float* sX = sH + SMF_H;
    float* sG = sX + SMF_X;
    float* sC = sG + SMF_G;

    const int tid = threadIdx.x;
    const int dir = blockIdx.x >> 6;
    const int u0 = (blockIdx.x & 63) << 3;

    for (int i = tid; i < 32 * 512; i += 256) {
        int rr = i >> 9, k = i & 511;
        float w = Whh[((size_t)dir * G4 + (rr >> 3) * Hn + u0 + (rr & 7)) * Hn + k];
        sW[k * SW_PITCH + rr] = w;
    }
    for (int i = tid; i < 512; i += 256) sC[i] = 0.f;

    const int r  = tid & 31;
    const int b0 = (tid >> 5) << 3;
    const int xr = tid >> 3;
    const int xc = (tid & 7) * 8;
    const int hr16 = tid >> 4;
    const int hc = (tid & 15) * 4;
    const int pb = tid & 63;
    const int pu = tid >> 6;

    {
        int t0 = dir ? (Tn - 1) : 0;
        const float* xp = xwT + ((size_t)dir * G4 + (xr >> 3) * Hn + u0 + (xr & 7)) * Mtot
                              + (size_t)t0 * Bn + xc;
        float4 x0 = __ldg((const float4*)xp);
        float4 x1 = __ldg((const float4*)(xp + 4));
        *(float4*)&sX[xr * SH_PITCH + xc] = x0;
        *(float4*)&sX[xr * SH_PITCH + xc + 4] = x1;
    }
    __syncthreads();

    unsigned* ctr = &g_barv[dir * 32];

#pragma unroll 1
    for (int s = 0; s < Tn; s++) {
        const int t = dir ? (Tn - 1 - s) : s;
        const float* hin = g_hT + (((size_t)(s & 1) * 2 + dir) << 15);

        ulonglong2 x01 = *(const ulonglong2*)&sX[r * SH_PITCH + b0];
        ulonglong2 x23 = *(const ulonglong2*)&sX[r * SH_PITCH + b0 + 4];
        unsigned long long acc0 = x01.x, acc1 = x01.y, acc2 = x23.x, acc3 = x23.y;

        float4 xf0, xf1;
        if (s + 1 < Tn) {
            int tnx = dir ? (Tn - 2 - s) : (s + 1);
            const float* xp = xwT + ((size_t)dir * G4 + (xr >> 3) * Hn + u0 + (xr & 7)) * Mtot
                                  + (size_t)tnx * Bn + xc;
            xf0 = __ldg((const float4*)xp);
            xf1 = __ldg((const float4*)(xp + 4));
        }

        {
            float4 c0 = __ldcg((const float4*)(hin + (size_t)(0 * 16 + hr16) * Bn + hc));
            float4 c1 = __ldcg((const float4*)(hin + (size_t)(1 * 16 + hr16) * Bn + hc));
            float4 c2 = __ldcg((const float4*)(hin + (size_t)(2 * 16 + hr16) * Bn + hc));
            float4 c3 = __ldcg((const float4*)(hin + (size_t)(3 * 16 + hr16) * Bn + hc));
            *(float4*)&sH[(0 * 16 + hr16) * SH_PITCH + hc] = c0;
            *(float4*)&sH[(1 * 16 + hr16) * SH_PITCH + hc] = c1;
            *(float4*)&sH[(2 * 16 + hr16) * SH_PITCH + hc] = c2;
            *(float4*)&sH[(3 * 16 + hr16) * SH_PITCH + hc] = c3;
        }
        __syncthreads();

#pragma unroll 2
        for (int i = 0; i < NCHUNK; i++) {
            float4 n0q, n1q, n2q, n3q;
            if (i + 1 < NCHUNK) {
                const float* hp = hin + (size_t)(i + 1) * 64 * Bn;
                n0q = __ldcg((const float4*)(hp + (size_t)(0 * 16 + hr16) * Bn + hc));
                n1q = __ldcg((const float4*)(hp + (size_t)(1 * 16 + hr16) * Bn + hc));
                n2q = __ldcg((const float4*)(hp + (size_t)(2 * 16 + hr16) * Bn + hc));
                n3q = __ldcg((const float4*)(hp + (size_t)(3 * 16 + hr16) * Bn + hc));
            }
            {
                const float* buf = sH + (i & 1) * (64 * SH_PITCH);
                const float* wp = sW + (i * 64) * SW_PITCH;
#pragma unroll 16
                for (int kk = 0; kk < 64; kk++) {
                    float w = wp[kk * SW_PITCH + r];
                    unsigned long long w2 = pk2(w, w);
                    ulonglong2 h01 = *(const ulonglong2*)&buf[kk * SH_PITCH + b0];
                    ulonglong2 h23 = *(const ulonglong2*)&buf[kk * SH_PITCH + b0 + 4];
                    fma2(acc0, h01.x, w2);
                    fma2(acc1, h01.y, w2);
                    fma2(acc2, h23.x, w2);
                    fma2(acc3, h23.y, w2);
                }
            }
            if (i + 1 < NCHUNK) {
                float* buf = sH + ((i + 1) & 1) * (64 * SH_PITCH);
                *(float4*)&buf[(0 * 16 + hr16) * SH_PITCH + hc] = n0q;
                *(float4*)&buf[(1 * 16 + hr16) * SH_PITCH + hc] = n1q;
                *(float4*)&buf[(2 * 16 + hr16) * SH_PITCH + hc] = n2q;
                *(float4*)&buf[(3 * 16 + hr16) * SH_PITCH + hc] = n3q;
            }
            if (i == 0 && s + 1 < Tn) {
                *(float4*)&sX[xr * SH_PITCH + xc] = xf0;
                *(float4*)&sX[xr * SH_PITCH + xc + 4] = xf1;
            }
            __syncthreads();
        }

        {
            float2 p0 = upk2(acc0), p1 = upk2(acc1), p2 = upk2(acc2), p3 = upk2(acc3);
            sG[r*66+b0+0]=p0.x; sG[r*66+b0+1]=p0.y; sG[r*66+b0+2]=p1.x; sG[r*66+b0+3]=p1.y;
            sG[r*66+b0+4]=p2.x; sG[r*66+b0+5]=p2.y; sG[r*66+b0+6]=p3.x; sG[r*66+b0+7]=p3.y;
        }
        __syncthreads();

        float* hTout = g_hT + (((size_t)((s + 1) & 1) * 2 + dir) << 15);
#pragma unroll
        for (int hh = 0; hh < 2; hh++) {
            int ul = pu + hh * 4;
            float iv = sG[(0 * 8 + ul) * 66 + pb];
            float fv = sG[(1 * 8 + ul) * 66 + pb];
            float gv = sG[(2 * 8 + ul) * 66 + pb];
            float ov = sG[(3 * 8 + ul) * 66 + pb];
            iv = 1.f / (1.f + expf(-iv));
            fv = 1.f / (1.f + expf(-fv));
            gv = tanhf(gv);
            ov = 1.f / (1.f + expf(-ov));
            float c = fv * sC[ul * 64 + pb] + iv * gv;
            c = fminf(fmaxf(c, -100.f), 100.f);
            float hv = ov * tanhf(c);
            sC[ul * 64 + pb] = c;
            hTout[(size_t)(u0 + ul) * Bn + pb] = hv;
            outT[((size_t)dir * Hn + u0 + ul) * Mtot + (size_t)t * Bn + pb] = hv;
        }

        if (s < Tn - 1) {
            __threadfence();
            __syncthreads();
            if (tid == 0) atomicAdd(ctr, 1u);
            unsigned target = 64u * (unsigned)(s + 1);
            while (ldacq(ctr) < target) {}
        }
    }
}

// ===================== attention logits =====================
__global__ __launch_bounds__(512)
void attn_logit_kernel(const float* __restrict__ h1T, const float* __restrict__ Wa,
                       const float* __restrict__ ba, float* __restrict__ logit) {
    __shared__ float sWa[Hn];
    __shared__ float red[8][64];
    const int t = blockIdx.x;
    const int ug = threadIdx.x >> 6, b = threadIdx.x & 63;
    sWa[threadIdx.x] = Wa[threadIdx.x];
    __syncthreads();

    float acc = 0.f;
    const size_t moff = (size_t)t * Bn + b;
#pragma unroll 4
    for (int uu = 0; uu < 64; uu++) {
        int u = ug * 64 + uu;
        float hf = h1T[(size_t)u * Mtot + moff];
        float hb = h1T[((size_t)Hn + u) * Mtot + moff];
        acc += (hf + hb) * sWa[u];
    }
    red[ug][b] = acc;
    __syncthreads();
    if (ug == 0) {
        float s = ba[0];
#pragma unroll
        for (int g = 0; g < 8; g++) s += red[g][b];
        logit[t * Bn + b] = s;
    }
}

// ===================== softmax over t (CTA per b) =====================
__global__ __launch_bounds__(512)
void softmax_kernel(const float* __restrict__ logit, float* __restrict__ outp,
                    float* __restrict__ aT) {
    __shared__ float red[Tn];
    const int b = blockIdx.x, t = threadIdx.x;
    float v = logit[t * Bn + b];
    red[t] = v; __syncthreads();
    for (int st = 256; st > 0; st >>= 1) {
        if (t < st) red[t] = fmaxf(red[t], red[t + st]);
        __syncthreads();
    }
    float m = red[0]; __syncthreads();
    float e = expf(v - m);
    red[t] = e; __syncthreads();
    for (int st = 256; st > 0; st >>= 1) {
        if (t < st) red[t] += red[t + st];
        __syncthreads();
    }
    float a = e / red[0];
    outp[Bn * NOUT + b * Tn + t] = a;
    aT[t * Bn + b] = a;
}

// ===================== attention pooling (CTA per u) =====================
__global__ __launch_bounds__(64)
void pool_kernel(const float* __restrict__ h1T, const float* __restrict__ aT,
                 float* __restrict__ pooledT) {
    const int u = blockIdx.x, b = threadIdx.x;
    const float* hf = h1T + (size_t)u * Mtot;
    const float* hb = h1T + ((size_t)Hn + u) * Mtot;
    float acc = 0.f;
#pragma unroll 4
    for (int t = 0; t < Tn; t++) {
        acc += (hf[t * Bn + b] + hb[t * Bn + b]) * aT[t * Bn + b];
    }
    pooledT[u * Bn + b] = acc;
}

// ===================== output head (CTA per b) =====================
__global__ __launch_bounds__(128)
void pred_kernel(const float* __restrict__ pooledT, const float* __restrict__ Wo,
                 const float* __restrict__ bo, float* __restrict__ outp) {
    __shared__ float sp[Hn];
    const int b = blockIdx.x, o = threadIdx.x;
    for (int u = o; u < Hn; u += 128) sp[u] = pooledT[u * Bn + b];
    __syncthreads();
    float s = bo[o];
    const float* wp = Wo + (size_t)o * Hn;
#pragma unroll 4
    for (int u = 0; u < Hn; u++) s += sp[u] * wp[u];
    outp[b * NOUT + o] = s;
}

// ===================== launch =====================
extern "C" void kernel_launch(void* const* d_in, const int* in_sizes, int n_in,
                              void* d_out, int out_size) {
    (void)in_sizes; (void)n_in; (void)out_size;
    const float* input = (const float*)d_in[0];
    const float* Wih0  = (const float*)d_in[1];
    const float* Whh0  = (const float*)d_in[2];
    const float* b0    = (const float*)d_in[3];
    const float* Wih1  = (const float*)d_in[4];
    const float* Whh1  = (const float*)d_in[5];
    const float* b1    = (const float*)d_in[6];
    const float* Wa    = (const float*)d_in[7];
    const float* ba    = (const float*)d_in[8];
    const float* Wo    = (const float*)d_in[9];
    const float* bo    = (const float*)d_in[10];
    float* outp = (float*)d_out;

    float *xw, *out0, *out1, *logit, *aT, *pooledT;
    __nv_bfloat16 *xhi, *xlo, *whi, *wlo;
    cudaGetSymbolAddress((void**)&xw, g_xw);
    cudaGetSymbolAddress((void**)&out0, g_out0);
    cudaGetSymbolAddress((void**)&out1, g_out1);
    cudaGetSymbolAddress((void**)&logit, g_logit);
    cudaGetSymbolAddress((void**)&aT, g_attnT);
    cudaGetSymbolAddress((void**)&pooledT, g_pooledT);
    cudaGetSymbolAddress((void**)&xhi, g_xhi);
    cudaGetSymbolAddress((void**)&xlo, g_xlo);
    cudaGetSymbolAddress((void**)&whi, g_whi);
    cudaGetSymbolAddress((void**)&wlo, g_wlo);

    cudaFuncSetAttribute(lstm_kernel, cudaFuncAttributeMaxDynamicSharedMemorySize,
                         LSTM_SMEM_BYTES);
    cudaFuncSetAttribute(mma_gemm_kernel, cudaFuncAttributeMaxDynamicSharedMemorySize,
                         GEMM_SMEM);

    dim3 mgrid(32, 256);   // 32 n-tiles (4096/128), 256 m-tiles

    // ---- layer 0 ----
    convert_split_kernel<<<2048, 256>>>(Wih0, whi, wlo, 2 * G4 * 256);
    convert_split_kernel<<<4096, 256>>>(input, xhi, xlo, Mtot * 256);
    mma_gemm_kernel<<<mgrid, 256, GEMM_SMEM>>>(whi, wlo, xhi, xlo, b0, xw, 256);
    init_kernel<<<64, 256>>>();
    lstm_kernel<<<NCTA_LSTM, 256, LSTM_SMEM_BYTES>>>(xw, Whh0, out0);

    // ---- layer 1 ----
    convert_split_kernel<<<4096, 256>>>(Wih1, whi, wlo, 2 * G4 * 1024);
    transpose_split_kernel<<<dim3(1024, 32), dim3(32, 8)>>>(out0, xhi, xlo);
    mma_gemm_kernel<<<mgrid, 256, GEMM_SMEM>>>(whi, wlo, xhi, xlo, b1, xw, 1024);
    init_kernel<<<64, 256>>>();
    lstm_kernel<<<NCTA_LSTM, 256, LSTM_SMEM_BYTES>>>(xw, Whh1, out1);

    // ---- attention + head ----
    attn_logit_kernel<<<Tn, 512>>>(out1, Wa, ba, logit);
    softmax_kernel<<<Bn, Tn>>>(logit, outp, aT);
    pool_kernel<<<Hn, Bn>>>(out1, aT, pooledT);
    pred_kernel<<<Bn, NOUT>>>(pooledT, Wo, bo, outp);
}

// round 9
// speedup vs baseline: 2.7449x; 1.6952x over previous
#include <cuda_runtime.h>
#include <cuda_bf16.h>
#include <cstdint>
#include <math.h>

#define Tn   512
#define Bn   64
#define Hn   512
#define G4   2048
#define NOUT 128
#define Mtot (Tn * Bn)          // 32768
#define NCTA_LSTM 128

// ---------------- scratch ----------------
__device__ float g_xw[(size_t)2 * G4 * Mtot];        // xw_T[dir][n][m]
__device__ float g_out0[(size_t)2 * Hn * Mtot];      // out0_T[dir][u][m]
__device__ float g_out1[(size_t)2 * Hn * Mtot];      // out1_T[dir][u][m]
__device__ float g_logit[Tn * Bn];
__device__ float g_attnT[Tn * Bn];
__device__ float g_pooledT[Hn * Bn];
__device__ unsigned g_barv[64];
// h exchange buffers: [buf2][dir2][part2][b64][k512] bf16
__device__ __nv_bfloat16 g_hbf[2 * 2 * 2 * 64 * 512];
// bf16 split buffers for the big GEMM
__device__ __nv_bfloat16 g_xhi[(size_t)Mtot * 1024];
__device__ __nv_bfloat16 g_xlo[(size_t)Mtot * 1024];
__device__ __nv_bfloat16 g_whi[2 * G4 * 1024];
__device__ __nv_bfloat16 g_wlo[2 * G4 * 1024];

__device__ __forceinline__ unsigned ldacq(const unsigned* p) {
    unsigned v;
    asm volatile("ld.acquire.gpu.global.b32 %0, [%1];" : "=r"(v) : "l"(p) : "memory");
    return v;
}

// ==================== mma.sync helpers ====================
__device__ __forceinline__ unsigned smem_u32(const void* p) {
    unsigned a;
    asm("{ .reg .u64 t; cvta.to.shared.u64 t, %1; cvt.u32.u64 %0, t; }" : "=r"(a) : "l"(p));
    return a;
}
__device__ __forceinline__ void ldsm4(unsigned& r0, unsigned& r1, unsigned& r2, unsigned& r3,
                                      unsigned addr) {
    asm volatile("ldmatrix.sync.aligned.m8n8.x4.shared.b16 {%0,%1,%2,%3}, [%4];"
                 : "=r"(r0), "=r"(r1), "=r"(r2), "=r"(r3) : "r"(addr));
}
__device__ __forceinline__ void ldsm2(unsigned& r0, unsigned& r1, unsigned addr) {
    asm volatile("ldmatrix.sync.aligned.m8n8.x2.shared.b16 {%0,%1}, [%2];"
                 : "=r"(r0), "=r"(r1) : "r"(addr));
}
__device__ __forceinline__ void mma16816(float* c, const unsigned* a, unsigned b0, unsigned b1) {
    asm volatile(
        "mma.sync.aligned.m16n8k16.row.col.f32.bf16.bf16.f32 "
        "{%0,%1,%2,%3}, {%4,%5,%6,%7}, {%8,%9}, {%0,%1,%2,%3};"
        : "+f"(c[0]), "+f"(c[1]), "+f"(c[2]), "+f"(c[3])
        : "r"(a[0]), "r"(a[1]), "r"(a[2]), "r"(a[3]), "r"(b0), "r"(b1));
}
__device__ __forceinline__ void cpasync16(unsigned dst, const void* src) {
    asm volatile("cp.async.cg.shared.global [%0], [%1], 16;" :: "r"(dst), "l"(src));
}
__device__ __forceinline__ void cpasync_commit() {
    asm volatile("cp.async.commit_group;" ::: "memory");
}
__device__ __forceinline__ void cpasync_wait0() {
    asm volatile("cp.async.wait_group 0;" ::: "memory");
}

// ==================== fp32 -> bf16 hi/lo converters ====================
__global__ void convert_split_kernel(const float* __restrict__ in,
                                     __nv_bfloat16* __restrict__ hi,
                                     __nv_bfloat16* __restrict__ lo, int n) {
    int i = blockIdx.x * blockDim.x + threadIdx.x;
    for (; i < n; i += gridDim.x * blockDim.x) {
        float v = in[i];
        __nv_bfloat16 h = __float2bfloat16_rn(v);
        hi[i] = h;
        lo[i] = __float2bfloat16_rn(v - __bfloat162float(h));
    }
}

// transpose-convert: in[k][m] fp32 (k=1024, m=32768) -> hi/lo[m][k]
__global__ __launch_bounds__(256)
void transpose_split_kernel(const float* __restrict__ in,
                            __nv_bfloat16* __restrict__ hi,
                            __nv_bfloat16* __restrict__ lo) {
    __shared__ float s[32][33];
    const int m0 = blockIdx.x * 32, k0 = blockIdx.y * 32;
    const int tx = threadIdx.x, ty = threadIdx.y;  // 32 x 8
#pragma unroll
    for (int j = 0; j < 4; j++)
        s[ty + 8 * j][tx] = in[(size_t)(k0 + ty + 8 * j) * Mtot + m0 + tx];
    __syncthreads();
#pragma unroll
    for (int j = 0; j < 4; j++) {
        float v = s[tx][ty + 8 * j];
        __nv_bfloat16 h = __float2bfloat16_rn(v);
        size_t o = (size_t)(m0 + ty + 8 * j) * 1024 + k0 + tx;
        hi[o] = h;
        lo[o] = __float2bfloat16_rn(v - __bfloat162float(h));
    }
}

// ==================== mma.sync GEMM (unchanged from R7) ====================
#define GP      72
#define GTILE   (128 * GP * 2)
#define GBUF    (4 * GTILE)
#define GEMM_SMEM (2 * GBUF)

__global__ __launch_bounds__(256, 1)
void mma_gemm_kernel(const __nv_bfloat16* __restrict__ Whi, const __nv_bfloat16* __restrict__ Wlo,
                     const __nv_bfloat16* __restrict__ Xhi, const __nv_bfloat16* __restrict__ Xlo,
                     const float* __restrict__ bias, float* __restrict__ C, int K) {
    extern __shared__ char smem[];
    const unsigned sb = smem_u32(smem);
    const int tid = threadIdx.x;
    const int wid = tid >> 5, lane = tid & 31;
    const int wa = wid & 3;
    const int wb = wid >> 2;
    const int n0 = blockIdx.x * 128;
    const int m0 = blockIdx.y * 128;
    const int NC = K >> 6;

    const __nv_bfloat16* gsrc[4] = {Whi + (size_t)n0 * K, Wlo + (size_t)n0 * K,
                                    Xhi + (size_t)m0 * K, Xlo + (size_t)m0 * K};

    float acc[2][8][4];
#pragma unroll
    for (int i = 0; i < 2; i++)
#pragma unroll
        for (int j = 0; j < 8; j++)
#pragma unroll
            for (int q = 0; q < 4; q++) acc[i][j][q] = 0.f;

#pragma unroll
    for (int tgt = 0; tgt < 4; tgt++) {
#pragma unroll
        for (int i = 0; i < 4; i++) {
            int lin = tid + i * 256;
            int row = lin >> 3, unit = lin & 7;
            cpasync16(sb + tgt * GTILE + (row * GP + unit * 8) * 2,
                      gsrc[tgt] + (size_t)row * K + unit * 8);
        }
    }
    cpasync_commit();

    const int a_roff = (lane & 7) + ((lane >> 3) & 1) * 8;
    const int a_koff = ((lane >> 4) & 1) * 8;
    const int b_roff = (lane & 7) + ((lane >> 4) & 1) * 8;
    const int b_koff = ((lane >> 3) & 1) * 8;

#pragma unroll 1
    for (int c = 0; c < NC; c++) {
        cpasync_wait0();
        __syncthreads();
        if (c + 1 < NC) {
            const int kc = (c + 1) * 64;
            const unsigned bo = ((c + 1) & 1) * GBUF;
#pragma unroll
            for (int tgt = 0; tgt < 4; tgt++) {
#pragma unroll
                for (int i = 0; i < 4; i++) {
                    int lin = tid + i * 256;
                    int row = lin >> 3, unit = lin & 7;
                    cpasync16(sb + bo + tgt * GTILE + (row * GP + unit * 8) * 2,
                              gsrc[tgt] + (size_t)row * K + kc + unit * 8);
                }
            }
            cpasync_commit();
        }
        const unsigned cb = (c & 1) * GBUF;
#pragma unroll
        for (int ks = 0; ks < 4; ks++) {
            const int k0 = ks * 16;
            unsigned ahi[2][4], alo[2][4], bhi[4][4], blo[4][4];
#pragma unroll
            for (int mf = 0; mf < 2; mf++) {
                int row = wa * 32 + mf * 16 + a_roff;
                unsigned ad = sb + cb + (row * GP + k0 + a_koff) * 2;
                ldsm4(ahi[mf][0], ahi[mf][1], ahi[mf][2], ahi[mf][3], ad);
                ldsm4(alo[mf][0], alo[mf][1], alo[mf][2], alo[mf][3], ad + GTILE);
            }
#pragma unroll
            for (int nf = 0; nf < 4; nf++) {
                int row = wb * 64 + nf * 16 + b_roff;
                unsigned ad = sb + cb + 2 * GTILE + (row * GP + k0 + b_koff) * 2;
                ldsm4(bhi[nf][0], bhi[nf][1], bhi[nf][2], bhi[nf][3], ad);
                ldsm4(blo[nf][0], blo[nf][1], blo[nf][2], blo[nf][3], ad + GTILE);
            }
#pragma unroll
            for (int mf = 0; mf < 2; mf++)
#pragma unroll
                for (int nf = 0; nf < 4; nf++)
#pragma unroll
                    for (int hf = 0; hf < 2; hf++) {
                        float* cc = acc[mf][nf * 2 + hf];
                        mma16816(cc, ahi[mf], bhi[nf][hf * 2], bhi[nf][hf * 2 + 1]);
                        mma16816(cc, ahi[mf], blo[nf][hf * 2], blo[nf][hf * 2 + 1]);
                        mma16816(cc, alo[mf], bhi[nf][hf * 2], bhi[nf][hf * 2 + 1]);
                    }
        }
        __syncthreads();
    }

    const int g = lane >> 2, tig = lane & 3;
#pragma unroll
    for (int mf = 0; mf < 2; mf++) {
        const int nr = n0 + wa * 32 + mf * 16 + g;
        const float bv0 = bias[nr];
        const float bv1 = bias[nr + 8];
#pragma unroll
        for (int j = 0; j < 8; j++) {
            const int mcol = m0 + wb * 64 + j * 8 + tig * 2;
            float2 v0 = make_float2(acc[mf][j][0] + bv0, acc[mf][j][1] + bv0);
            float2 v1 = make_float2(acc[mf][j][2] + bv1, acc[mf][j][3] + bv1);
            *(float2*)&C[(size_t)nr * Mtot + mcol] = v0;
            *(float2*)&C[(size_t)(nr + 8) * Mtot + mcol] = v1;
        }
    }
}

// ===================== init: zero h bf16 buffers + barrier counters =====================
__global__ void init_kernel() {
    int i = blockIdx.x * blockDim.x + threadIdx.x;
    if (i < 64) g_barv[i] = 0u;
    uint4* p = (uint4*)g_hbf;
    const int n = (2 * 2 * 2 * 64 * 512) / 8;   // uint4 = 8 bf16
    for (int j = i; j < n; j += gridDim.x * blockDim.x)
        p[j] = make_uint4(0u, 0u, 0u, 0u);
}

// ===================== tensor-core persistent LSTM layer =====================
// CTA = (dir, 8 units) -> 32 gate rows. Warp w owns batches w*8..w*8+7.
// gates[32][64] = Whh_bf16split[32][512] @ h_bf16split[512][64], fp32 accum.
// smem: A hi/lo [32][520], B hi/lo [64][520] bf16 (pad 8 halves -> conflict-free ldmatrix)
#define LAP 520
#define LSTM2_SMEM ((2 * 32 * LAP + 2 * 64 * LAP) * 2)   // 199680 B

__global__ __launch_bounds__(256, 1)
void lstm_mma_kernel(const float* __restrict__ xwT, const float* __restrict__ Whh,
                     float* __restrict__ outT) {
    extern __shared__ __nv_bfloat16 sbuf[];
    __nv_bfloat16* sAhi = sbuf;                    // [32][520]
    __nv_bfloat16* sAlo = sAhi + 32 * LAP;
    __nv_bfloat16* sBhi = sAlo + 32 * LAP;         // [64][520]
    __nv_bfloat16* sBlo = sBhi + 64 * LAP;

    const int tid = threadIdx.x;
    const int wid = tid >> 5, lane = tid & 31;
    const int dir = blockIdx.x >> 6;
    const int u0 = (blockIdx.x & 63) << 3;

    // load + split Whh slice into smem (row r = gate*8 + ul)
    for (int i = tid; i < 32 * 512; i += 256) {
        int r = i >> 9, k = i & 511;
        int gate = r >> 3, ul = r & 7;
        float w = Whh[((size_t)dir * G4 + gate * Hn + u0 + ul) * Hn + k];
        __nv_bfloat16 h = __float2bfloat16_rn(w);
        sAhi[r * LAP + k] = h;
        sAlo[r * LAP + k] = __float2bfloat16_rn(w - __bfloat162float(h));
    }

    const unsigned aAhi = smem_u32(sAhi);
    const unsigned aAlo = smem_u32(sAlo);
    const unsigned aBhi = smem_u32(sBhi);
    const unsigned aBlo = smem_u32(sBlo);

    // fragment lane addressing (identical formulas to the proven GEMM)
    const int a_roff = (lane & 7) + ((lane >> 3) & 1) * 8;
    const int a_koff = ((lane >> 4) & 1) * 8;
    const int b_roff = lane & 7;
    const int b_koff = ((lane >> 3) & 1) * 8;

    const int g = lane >> 2;             // unit-local; acc rows {g,g+8,g+16,g+24}
    const int tig = lane & 3;
    const int bb = wid * 8 + tig * 2;    // first of this thread's 2 batches

    float c0 = 0.f, c1 = 0.f;            // cell state in registers
    unsigned* ctr = &g_barv[dir * 32];

    const size_t xrow = (size_t)dir * G4 + u0 + g;

#pragma unroll 1
    for (int s = 0; s < Tn; s++) {
        const int t = dir ? (Tn - 1 - s) : s;
        const size_t mo = (size_t)t * Bn + bb;

        // prefetch xw for all 4 gates (fp32, exact)
        float2 xwi = __ldg((const float2*)&xwT[(xrow + 0 * Hn) * Mtot + mo]);
        float2 xwf = __ldg((const float2*)&xwT[(xrow + 1 * Hn) * Mtot + mo]);
        float2 xwg = __ldg((const float2*)&xwT[(xrow + 2 * Hn) * Mtot + mo]);
        float2 xwo = __ldg((const float2*)&xwT[(xrow + 3 * Hn) * Mtot + mo]);

        // stage h(s) bf16 hi/lo into smem [b][k] (pad LAP)
        {
            const __nv_bfloat16* ghhi = g_hbf + ((((size_t)(s & 1) * 2 + dir) * 2 + 0) << 15);
            const __nv_bfloat16* ghlo = g_hbf + ((((size_t)(s & 1) * 2 + dir) * 2 + 1) << 15);
#pragma unroll
            for (int it = 0; it < 16; it++) {
                int i = tid + it * 256;
                int b = i >> 6, j = (i & 63) * 8;
                cpasync16(aBhi + (b * LAP + j) * 2, ghhi + b * 512 + j);
                cpasync16(aBlo + (b * LAP + j) * 2, ghlo + b * 512 + j);
            }
            cpasync_commit();
            cpasync_wait0();
        }
        __syncthreads();

        float acc0[4] = {0.f, 0.f, 0.f, 0.f};   // rows g(i), g+8(f)
        float acc1[4] = {0.f, 0.f, 0.f, 0.f};   // rows 16+g(g), 24+g(o)

#pragma unroll 8
        for (int ks = 0; ks < 32; ks++) {
            const int k0 = ks * 16;
            unsigned ah0[4], ah1[4], al0[4], al1[4];
            {
                unsigned ad = aAhi + ((a_roff) * LAP + k0 + a_koff) * 2;
                ldsm4(ah0[0], ah0[1], ah0[2], ah0[3], ad);
                ldsm4(ah1[0], ah1[1], ah1[2], ah1[3], ad + 16 * LAP * 2);
            }
            {
                unsigned ad = aAlo + ((a_roff) * LAP + k0 + a_koff) * 2;
                ldsm4(al0[0], al0[1], al0[2], al0[3], ad);
                ldsm4(al1[0], al1[1], al1[2], al1[3], ad + 16 * LAP * 2);
            }
            unsigned bh0, bh1, bl0, bl1;
            ldsm2(bh0, bh1, aBhi + ((wid * 8 + b_roff) * LAP + k0 + b_koff) * 2);
            ldsm2(bl0, bl1, aBlo + ((wid * 8 + b_roff) * LAP + k0 + b_koff) * 2);

            mma16816(acc0, ah0, bh0, bh1);
            mma16816(acc0, ah0, bl0, bl1);
            mma16816(acc0, al0, bh0, bh1);
            mma16816(acc1, ah1, bh0, bh1);
            mma16816(acc1, ah1, bl0, bl1);
            mma16816(acc1, al1, bh0, bh1);
        }

        // pointwise entirely in registers: i=acc0[0,1], f=acc0[2,3], g=acc1[0,1], o=acc1[2,3]
        float pi0 = acc0[0] + xwi.x, pi1 = acc0[1] + xwi.y;
        float pf0 = acc0[2] + xwf.x, pf1 = acc0[3] + xwf.y;
        float pg0 = acc1[0] + xwg.x, pg1 = acc1[1] + xwg.y;
        float po0 = acc1[2] + xwo.x, po1 = acc1[3] + xwo.y;

        float i0 = 1.f / (1.f + expf(-pi0)), i1 = 1.f / (1.f + expf(-pi1));
        float f0 = 1.f / (1.f + expf(-pf0)), f1 = 1.f / (1.f + expf(-pf1));
        float gg0 = tanhf(pg0), gg1 = tanhf(pg1);
        float o0 = 1.f / (1.f + expf(-po0)), o1 = 1.f / (1.f + expf(-po1));

        c0 = fminf(fmaxf(f0 * c0 + i0 * gg0, -100.f), 100.f);
        c1 = fminf(fmaxf(f1 * c1 + i1 * gg1, -100.f), 100.f);
        float h0 = o0 * tanhf(c0);
        float h1 = o1 * tanhf(c1);

        // fp32 layer output
        *(float2*)&outT[((size_t)dir * Hn + u0 + g) * Mtot + mo] = make_float2(h0, h1);

        // bf16 hi/lo h for next step, layout [b][k=unit]
        {
            __nv_bfloat16* whhi = g_hbf + ((((size_t)((s + 1) & 1) * 2 + dir) * 2 + 0) << 15);
            __nv_bfloat16* whlo = g_hbf + ((((size_t)((s + 1) & 1) * 2 + dir) * 2 + 1) << 15);
            __nv_bfloat16 h0h = __float2bfloat16_rn(h0);
            __nv_bfloat16 h1h = __float2bfloat16_rn(h1);
            whhi[(size_t)bb * 512 + u0 + g] = h0h;
            whhi[(size_t)(bb + 1) * 512 + u0 + g] = h1h;
            whlo[(size_t)bb * 512 + u0 + g] = __float2bfloat16_rn(h0 - __bfloat162float(h0h));
            whlo[(size_t)(bb + 1) * 512 + u0 + g] = __float2bfloat16_rn(h1 - __bfloat162float(h1h));
        }

        // per-direction grid barrier
        if (s < Tn - 1) {
            __threadfence();
            __syncthreads();
            if (tid == 0) atomicAdd(ctr, 1u);
            unsigned target = 64u * (unsigned)(s + 1);
            while (ldacq(ctr) < target) {}
        }
    }
}

// ===================== attention logits =====================
__global__ __launch_bounds__(512)
void attn_logit_kernel(const float* __restrict__ h1T, const float* __restrict__ Wa,
                       const float* __restrict__ ba, float* __restrict__ logit) {
    __shared__ float sWa[Hn];
    __shared__ float red[8][64];
    const int t = blockIdx.x;
    const int ug = threadIdx.x >> 6, b = threadIdx.x & 63;
    sWa[threadIdx.x] = Wa[threadIdx.x];
    __syncthreads();

    float acc = 0.f;
    const size_t moff = (size_t)t * Bn + b;
#pragma unroll 4
    for (int uu = 0; uu < 64; uu++) {
        int u = ug * 64 + uu;
        float hf = h1T[(size_t)u * Mtot + moff];
        float hb = h1T[((size_t)Hn + u) * Mtot + moff];
        acc += (hf + hb) * sWa[u];
    }
    red[ug][b] = acc;
    __syncthreads();
    if (ug == 0) {
        float s = ba[0];
#pragma unroll
        for (int g = 0; g < 8; g++) s += red[g][b];
        logit[t * Bn + b] = s;
    }
}

// ===================== softmax over t (CTA per b) =====================
__global__ __launch_bounds__(512)
void softmax_kernel(const float* __restrict__ logit, float* __restrict__ outp,
                    float* __restrict__ aT) {
    __shared__ float red[Tn];
    const int b = blockIdx.x, t = threadIdx.x;
    float v = logit[t * Bn + b];
    red[t] = v; __syncthreads();
    for (int st = 256; st > 0; st >>= 1) {
        if (t < st) red[t] = fmaxf(red[t], red[t + st]);
        __syncthreads();
    }
    float m = red[0]; __syncthreads();
    float e = expf(v - m);
    red[t] = e; __syncthreads();
    for (int st = 256; st > 0; st >>= 1) {
        if (t < st) red[t] += red[t + st];
        __syncthreads();
    }
    float a = e / red[0];
    outp[Bn * NOUT + b * Tn + t] = a;
    aT[t * Bn + b] = a;
}

// ===================== attention pooling (CTA per u) =====================
__global__ __launch_bounds__(64)
void pool_kernel(const float* __restrict__ h1T, const float* __restrict__ aT,
                 float* __restrict__ pooledT) {
    const int u = blockIdx.x, b = threadIdx.x;
    const float* hf = h1T + (size_t)u * Mtot;
    const float* hb = h1T + ((size_t)Hn + u) * Mtot;
    float acc = 0.f;
#pragma unroll 4
    for (int t = 0; t < Tn; t++) {
        acc += (hf[t * Bn + b] + hb[t * Bn + b]) * aT[t * Bn + b];
    }
    pooledT[u * Bn + b] = acc;
}

// ===================== output head (CTA per b) =====================
__global__ __launch_bounds__(128)
void pred_kernel(const float* __restrict__ pooledT, const float* __restrict__ Wo,
                 const float* __restrict__ bo, float* __restrict__ outp) {
    __shared__ float sp[Hn];
    const int b = blockIdx.x, o = threadIdx.x;
    for (int u = o; u < Hn; u += 128) sp[u] = pooledT[u * Bn + b];
    __syncthreads();
    float s = bo[o];
    const float* wp = Wo + (size_t)o * Hn;
#pragma unroll 4
    for (int u = 0; u < Hn; u++) s += sp[u] * wp[u];
    outp[b * NOUT + o] = s;
}

// ===================== launch =====================
extern "C" void kernel_launch(void* const* d_in, const int* in_sizes, int n_in,
                              void* d_out, int out_size) {
    (void)in_sizes; (void)n_in; (void)out_size;
    const float* input = (const float*)d_in[0];
    const float* Wih0  = (const float*)d_in[1];
    const float* Whh0  = (const float*)d_in[2];
    const float* b0    = (const float*)d_in[3];
    const float* Wih1  = (const float*)d_in[4];
    const float* Whh1  = (const float*)d_in[5];
    const float* b1    = (const float*)d_in[6];
    const float* Wa    = (const float*)d_in[7];
    const float* ba    = (const float*)d_in[8];
    const float* Wo    = (const float*)d_in[9];
    const float* bo    = (const float*)d_in[10];
    float* outp = (float*)d_out;

    float *xw, *out0, *out1, *logit, *aT, *pooledT;
    __nv_bfloat16 *xhi, *xlo, *whi, *wlo;
    cudaGetSymbolAddress((void**)&xw, g_xw);
    cudaGetSymbolAddress((void**)&out0, g_out0);
    cudaGetSymbolAddress((void**)&out1, g_out1);
    cudaGetSymbolAddress((void**)&logit, g_logit);
    cudaGetSymbolAddress((void**)&aT, g_attnT);
    cudaGetSymbolAddress((void**)&pooledT, g_pooledT);
    cudaGetSymbolAddress((void**)&xhi, g_xhi);
    cudaGetSymbolAddress((void**)&xlo, g_xlo);
    cudaGetSymbolAddress((void**)&whi, g_whi);
    cudaGetSymbolAddress((void**)&wlo, g_wlo);

    cudaFuncSetAttribute(lstm_mma_kernel, cudaFuncAttributeMaxDynamicSharedMemorySize,
                         LSTM2_SMEM);
    cudaFuncSetAttribute(mma_gemm_kernel, cudaFuncAttributeMaxDynamicSharedMemorySize,
                         GEMM_SMEM);

    dim3 mgrid(32, 256);   // 32 n-tiles (4096/128), 256 m-tiles

    // ---- layer 0 ----
    convert_split_kernel<<<2048, 256>>>(Wih0, whi, wlo, 2 * G4 * 256);
    convert_split_kernel<<<4096, 256>>>(input, xhi, xlo, Mtot * 256);
    mma_gemm_kernel<<<mgrid, 256, GEMM_SMEM>>>(whi, wlo, xhi, xlo, b0, xw, 256);
    init_kernel<<<64, 256>>>();
    lstm_mma_kernel<<<NCTA_LSTM, 256, LSTM2_SMEM>>>(xw, Whh0, out0);

    // ---- layer 1 ----
    convert_split_kernel<<<4096, 256>>>(Wih1, whi, wlo, 2 * G4 * 1024);
    transpose_split_kernel<<<dim3(1024, 32), dim3(32, 8)>>>(out0, xhi, xlo);
    mma_gemm_kernel<<<mgrid, 256, GEMM_SMEM>>>(whi, wlo, xhi, xlo, b1, xw, 1024);
    init_kernel<<<64, 256>>>();
    lstm_mma_kernel<<<NCTA_LSTM, 256, LSTM2_SMEM>>>(xw, Whh1, out1);

    // ---- attention + head ----
    attn_logit_kernel<<<Tn, 512>>>(out1, Wa, ba, logit);
    softmax_kernel<<<Bn, Tn>>>(logit, outp, aT);
    pool_kernel<<<Hn, Bn>>>(out1, aT, pooledT);
    pred_kernel<<<Bn, NOUT>>>(pooledT, Wo, bo, outp);
}

// round 11
// speedup vs baseline: 3.1043x; 1.1309x over previous
#include <cuda_runtime.h>
#include <cuda_bf16.h>
#include <cuda_fp16.h>
#include <cstdint>
#include <math.h>

#define Tn   512
#define Bn   64
#define Hn   512
#define G4   2048
#define NOUT 128
#define Mtot (Tn * Bn)          // 32768
#define NCTA_LSTM 128

// ---------------- scratch ----------------
__device__ float g_xw[(size_t)2 * G4 * Mtot];        // xw_T[dir][n][m]
__device__ float g_out0[(size_t)2 * Hn * Mtot];      // out0_T[dir][u][m]
__device__ float g_out1[(size_t)2 * Hn * Mtot];      // out1_T[dir][u][m]
__device__ float g_logit[Tn * Bn];
__device__ float g_attnT[Tn * Bn];
__device__ float g_pooledT[Hn * Bn];
__device__ unsigned g_barv[64];
// h exchange buffers: [buf2][dir2][b64][k512] fp16
__device__ __half g_hbf[2 * 2 * 64 * 512];
// bf16 split buffers for the big GEMM
__device__ __nv_bfloat16 g_xhi[(size_t)Mtot * 1024];
__device__ __nv_bfloat16 g_xlo[(size_t)Mtot * 1024];
__device__ __nv_bfloat16 g_whi[2 * G4 * 1024];
__device__ __nv_bfloat16 g_wlo[2 * G4 * 1024];

__device__ __forceinline__ unsigned ldacq(const unsigned* p) {
    unsigned v;
    asm volatile("ld.acquire.gpu.global.b32 %0, [%1];" : "=r"(v) : "l"(p) : "memory");
    return v;
}
__device__ __forceinline__ void red_release(unsigned* p) {
    asm volatile("red.release.gpu.global.add.u32 [%0], %1;" :: "l"(p), "r"(1u) : "memory");
}
__device__ __forceinline__ float sigf(float x) {
    return 1.f / (1.f + __expf(-x));
}
__device__ __forceinline__ float tanhfast(float x) {
    return 1.f - 2.f / (1.f + __expf(2.f * x));
}

// ==================== mma.sync helpers ====================
__device__ __forceinline__ unsigned smem_u32(const void* p) {
    unsigned a;
    asm("{ .reg .u64 t; cvta.to.shared.u64 t, %1; cvt.u32.u64 %0, t; }" : "=r"(a) : "l"(p));
    return a;
}
__device__ __forceinline__ void ldsm4(unsigned& r0, unsigned& r1, unsigned& r2, unsigned& r3,
                                      unsigned addr) {
    asm volatile("ldmatrix.sync.aligned.m8n8.x4.shared.b16 {%0,%1,%2,%3}, [%4];"
                 : "=r"(r0), "=r"(r1), "=r"(r2), "=r"(r3) : "r"(addr));
}
__device__ __forceinline__ void ldsm2(unsigned& r0, unsigned& r1, unsigned addr) {
    asm volatile("ldmatrix.sync.aligned.m8n8.x2.shared.b16 {%0,%1}, [%2];"
                 : "=r"(r0), "=r"(r1) : "r"(addr));
}
__device__ __forceinline__ void mma16816(float* c, const unsigned* a, unsigned b0, unsigned b1) {
    asm volatile(
        "mma.sync.aligned.m16n8k16.row.col.f32.bf16.bf16.f32 "
        "{%0,%1,%2,%3}, {%4,%5,%6,%7}, {%8,%9}, {%0,%1,%2,%3};"
        : "+f"(c[0]), "+f"(c[1]), "+f"(c[2]), "+f"(c[3])
        : "r"(a[0]), "r"(a[1]), "r"(a[2]), "r"(a[3]), "r"(b0), "r"(b1));
}
__device__ __forceinline__ void mma16816h(float* c, const unsigned* a, unsigned b0, unsigned b1) {
    asm volatile(
        "mma.sync.aligned.m16n8k16.row.col.f32.f16.f16.f32 "
        "{%0,%1,%2,%3}, {%4,%5,%6,%7}, {%8,%9}, {%0,%1,%2,%3};"
        : "+f"(c[0]), "+f"(c[1]), "+f"(c[2]), "+f"(c[3])
        : "r"(a[0]), "r"(a[1]), "r"(a[2]), "r"(a[3]), "r"(b0), "r"(b1));
}
__device__ __forceinline__ void cpasync16(unsigned dst, const void* src) {
    asm volatile("cp.async.cg.shared.global [%0], [%1], 16;" :: "r"(dst), "l"(src));
}
__device__ __forceinline__ void cpasync_commit() {
    asm volatile("cp.async.commit_group;" ::: "memory");
}
__device__ __forceinline__ void cpasync_wait0() {
    asm volatile("cp.async.wait_group 0;" ::: "memory");
}

// ==================== fp32 -> bf16 hi/lo converters ====================
__global__ void convert_split_kernel(const float* __restrict__ in,
                                     __nv_bfloat16* __restrict__ hi,
                                     __nv_bfloat16* __restrict__ lo, int n) {
    int i = blockIdx.x * blockDim.x + threadIdx.x;
    for (; i < n; i += gridDim.x * blockDim.x) {
        float v = in[i];
        __nv_bfloat16 h = __float2bfloat16_rn(v);
        hi[i] = h;
        lo[i] = __float2bfloat16_rn(v - __bfloat162float(h));
    }
}

// transpose-convert: in[k][m] fp32 (k=1024, m=32768) -> hi/lo[m][k]
__global__ __launch_bounds__(256)
void transpose_split_kernel(const float* __restrict__ in,
                            __nv_bfloat16* __restrict__ hi,
                            __nv_bfloat16* __restrict__ lo) {
    __shared__ float s[32][33];
    const int m0 = blockIdx.x * 32, k0 = blockIdx.y * 32;
    const int tx = threadIdx.x, ty = threadIdx.y;  // 32 x 8
#pragma unroll
    for (int j = 0; j < 4; j++)
        s[ty + 8 * j][tx] = in[(size_t)(k0 + ty + 8 * j) * Mtot + m0 + tx];
    __syncthreads();
#pragma unroll
    for (int j = 0; j < 4; j++) {
        float v = s[tx][ty + 8 * j];
        __nv_bfloat16 h = __float2bfloat16_rn(v);
        size_t o = (size_t)(m0 + ty + 8 * j) * 1024 + k0 + tx;
        hi[o] = h;
        lo[o] = __float2bfloat16_rn(v - __bfloat162float(h));
    }
}

// ==================== mma.sync GEMM (proven, unchanged) ====================
#define GP      72
#define GTILE   (128 * GP * 2)
#define GBUF    (4 * GTILE)
#define GEMM_SMEM (2 * GBUF)

__global__ __launch_bounds__(256, 1)
void mma_gemm_kernel(const __nv_bfloat16* __restrict__ Whi, const __nv_bfloat16* __restrict__ Wlo,
                     const __nv_bfloat16* __restrict__ Xhi, const __nv_bfloat16* __restrict__ Xlo,
                     const float* __restrict__ bias, float* __restrict__ C, int K) {
    extern __shared__ char smem[];
    const unsigned sb = smem_u32(smem);
    const int tid = threadIdx.x;
    const int wid = tid >> 5, lane = tid & 31;
    const int wa = wid & 3;
    const int wb = wid >> 2;
    const int n0 = blockIdx.x * 128;
    const int m0 = blockIdx.y * 128;
    const int NC = K >> 6;

    const __nv_bfloat16* gsrc[4] = {Whi + (size_t)n0 * K, Wlo + (size_t)n0 * K,
                                    Xhi + (size_t)m0 * K, Xlo + (size_t)m0 * K};

    float acc[2][8][4];
#pragma unroll
    for (int i = 0; i < 2; i++)
#pragma unroll
        for (int j = 0; j < 8; j++)
#pragma unroll
            for (int q = 0; q < 4; q++) acc[i][j][q] = 0.f;

#pragma unroll
    for (int tgt = 0; tgt < 4; tgt++) {
#pragma unroll
        for (int i = 0; i < 4; i++) {
            int lin = tid + i * 256;
            int row = lin >> 3, unit = lin & 7;
            cpasync16(sb + tgt * GTILE + (row * GP + unit * 8) * 2,
                      gsrc[tgt] + (size_t)row * K + unit * 8);
        }
    }
    cpasync_commit();

    const int a_roff = (lane & 7) + ((lane >> 3) & 1) * 8;
    const int a_koff = ((lane >> 4) & 1) * 8;
    const int b_roff = (lane & 7) + ((lane >> 4) & 1) * 8;
    const int b_koff = ((lane >> 3) & 1) * 8;

#pragma unroll 1
    for (int c = 0; c < NC; c++) {
        cpasync_wait0();
        __syncthreads();
        if (c + 1 < NC) {
            const int kc = (c + 1) * 64;
            const unsigned bo = ((c + 1) & 1) * GBUF;
#pragma unroll
            for (int tgt = 0; tgt < 4; tgt++) {
#pragma unroll
                for (int i = 0; i < 4; i++) {
                    int lin = tid + i * 256;
                    int row = lin >> 3, unit = lin & 7;
                    cpasync16(sb + bo + tgt * GTILE + (row * GP + unit * 8) * 2,
                              gsrc[tgt] + (size_t)row * K + kc + unit * 8);
                }
            }
            cpasync_commit();
        }
        const unsigned cb = (c & 1) * GBUF;
#pragma unroll
        for (int ks = 0; ks < 4; ks++) {
            const int k0 = ks * 16;
            unsigned ahi[2][4], alo[2][4], bhi[4][4], blo[4][4];
#pragma unroll
            for (int mf = 0; mf < 2; mf++) {
                int row = wa * 32 + mf * 16 + a_roff;
                unsigned ad = sb + cb + (row * GP + k0 + a_koff) * 2;
                ldsm4(ahi[mf][0], ahi[mf][1], ahi[mf][2], ahi[mf][3], ad);
                ldsm4(alo[mf][0], alo[mf][1], alo[mf][2], alo[mf][3], ad + GTILE);
            }
#pragma unroll
            for (int nf = 0; nf < 4; nf++) {
                int row = wb * 64 + nf * 16 + b_roff;
                unsigned ad = sb + cb + 2 * GTILE + (row * GP + k0 + b_koff) * 2;
                ldsm4(bhi[nf][0], bhi[nf][1], bhi[nf][2], bhi[nf][3], ad);
                ldsm4(blo[nf][0], blo[nf][1], blo[nf][2], blo[nf][3], ad + GTILE);
            }
#pragma unroll
            for (int mf = 0; mf < 2; mf++)
#pragma unroll
                for (int nf = 0; nf < 4; nf++)
#pragma unroll
                    for (int hf = 0; hf < 2; hf++) {
                        float* cc = acc[mf][nf * 2 + hf];
                        mma16816(cc, ahi[mf], bhi[nf][hf * 2], bhi[nf][hf * 2 + 1]);
                        mma16816(cc, ahi[mf], blo[nf][hf * 2], blo[nf][hf * 2 + 1]);
                        mma16816(cc, alo[mf], bhi[nf][hf * 2], bhi[nf][hf * 2 + 1]);
                    }
        }
        __syncthreads();
    }

    const int g = lane >> 2, tig = lane & 3;
#pragma unroll
    for (int mf = 0; mf < 2; mf++) {
        const int nr = n0 + wa * 32 + mf * 16 + g;
        const float bv0 = bias[nr];
        const float bv1 = bias[nr + 8];
#pragma unroll
        for (int j = 0; j < 8; j++) {
            const int mcol = m0 + wb * 64 + j * 8 + tig * 2;
            float2 v0 = make_float2(acc[mf][j][0] + bv0, acc[mf][j][1] + bv0);
            float2 v1 = make_float2(acc[mf][j][2] + bv1, acc[mf][j][3] + bv1);
            *(float2*)&C[(size_t)nr * Mtot + mcol] = v0;
            *(float2*)&C[(size_t)(nr + 8) * Mtot + mcol] = v1;
        }
    }
}

// ===================== init: zero h fp16 buffers + barrier counters =====================
__global__ void init_kernel() {
    int i = blockIdx.x * blockDim.x + threadIdx.x;
    if (i < 64) g_barv[i] = 0u;
    uint4* p = (uint4*)g_hbf;
    const int n = (2 * 2 * 64 * 512) / 8;   // uint4 = 8 halves
    for (int j = i; j < n; j += gridDim.x * blockDim.x)
        p[j] = make_uint4(0u, 0u, 0u, 0u);
}

// ===================== tensor-core persistent LSTM layer (fp16 2-term, scaled lo) =====================
// CTA = (dir, 8 units) -> 32 gate rows. Warp w owns batches w*8..w*8+7.
// gates[32][64] = (Whi + Wlo/1024)_fp16[32][512] @ h_fp16[512][64], fp32 accum;
// Wlo stored pre-scaled by 1024 (keeps it in fp16 normal range), separate accumulators.
#define LAP 520
#define LSTM2_SMEM ((2 * 32 * LAP + 64 * LAP) * 2)   // 133120 B
#define LO_SCALE 1024.0f
#define LO_INV   (1.0f / 1024.0f)

__global__ __launch_bounds__(256, 1)
void lstm_mma_kernel(const float* __restrict__ xwT, const float* __restrict__ Whh,
                     float* __restrict__ outT) {
    extern __shared__ __half hbuf[];
    __half* sAhi = hbuf;                    // [32][520]
    __half* sAlo = sAhi + 32 * LAP;
    __half* sB   = sAlo + 32 * LAP;         // [64][520]

    const int tid = threadIdx.x;
    const int wid = tid >> 5, lane = tid & 31;
    const int dir = blockIdx.x >> 6;
    const int u0 = (blockIdx.x & 63) << 3;

    // load + split Whh slice into smem (fp16 hi + 1024*lo, both normal range)
    for (int i = tid; i < 32 * 512; i += 256) {
        int r = i >> 9, k = i & 511;
        int gate = r >> 3, ul = r & 7;
        float w = Whh[((size_t)dir * G4 + gate * Hn + u0 + ul) * Hn + k];
        __half h = __float2half_rn(w);
        sAhi[r * LAP + k] = h;
        sAlo[r * LAP + k] = __float2half_rn((w - __half2float(h)) * LO_SCALE);
    }

    const unsigned aAhi = smem_u32(sAhi);
    const unsigned aAlo = smem_u32(sAlo);
    const unsigned aB   = smem_u32(sB);

    const int a_roff = (lane & 7) + ((lane >> 3) & 1) * 8;
    const int a_koff = ((lane >> 4) & 1) * 8;
    const int b_roff = lane & 7;
    const int b_koff = ((lane >> 3) & 1) * 8;

    const int g = lane >> 2;             // unit-local; acc rows {g,g+8,g+16,g+24}
    const int tig = lane & 3;
    const int bb = wid * 8 + tig * 2;    // first of this thread's 2 batches

    float c0 = 0.f, c1 = 0.f;            // cell state in registers
    unsigned* ctr = &g_barv[dir * 32];
    const size_t xrow = (size_t)dir * G4 + u0 + g;

#pragma unroll 1
    for (int s = 0; s < Tn; s++) {
        const int t = dir ? (Tn - 1 - s) : s;
        const size_t mo = (size_t)t * Bn + bb;

        // stage h(s) fp16 into smem [b][k]: 64 rows x 512 cols = 4096 x 8-half lines
        {
            const __half* gh = g_hbf + (((size_t)(s & 1) * 2 + dir) << 15);
#pragma unroll
            for (int it = 0; it < 16; it++) {
                int i = tid + it * 256;
                int b = i >> 6, j = (i & 63) * 8;
                cpasync16(aB + (b * LAP + j) * 2, gh + b * 512 + j);
            }
            cpasync_commit();
        }

        // xw for all 4 gates (fp32 exact) — overlaps cp.async flight
        float2 xwi = __ldg((const float2*)&xwT[(xrow + 0 * Hn) * Mtot + mo]);
        float2 xwf = __ldg((const float2*)&xwT[(xrow + 1 * Hn) * Mtot + mo]);
        float2 xwg = __ldg((const float2*)&xwT[(xrow + 2 * Hn) * Mtot + mo]);
        float2 xwo = __ldg((const float2*)&xwT[(xrow + 3 * Hn) * Mtot + mo]);

        cpasync_wait0();
        __syncthreads();

        float acc0h[4] = {0.f, 0.f, 0.f, 0.f};  // hi: rows g(i), g+8(f)
        float acc1h[4] = {0.f, 0.f, 0.f, 0.f};  // hi: rows 16+g(g), 24+g(o)
        float acc0l[4] = {0.f, 0.f, 0.f, 0.f};  // lo (scaled)
        float acc1l[4] = {0.f, 0.f, 0.f, 0.f};

#pragma unroll 8
        for (int ks = 0; ks < 32; ks++) {
            const int k0 = ks * 16;
            unsigned ah0[4], ah1[4], al0[4], al1[4];
            {
                unsigned ad = aAhi + ((a_roff) * LAP + k0 + a_koff) * 2;
                ldsm4(ah0[0], ah0[1], ah0[2], ah0[3], ad);
                ldsm4(ah1[0], ah1[1], ah1[2], ah1[3], ad + 16 * LAP * 2);
            }
            {
                unsigned ad = aAlo + ((a_roff) * LAP + k0 + a_koff) * 2;
                ldsm4(al0[0], al0[1], al0[2], al0[3], ad);
                ldsm4(al1[0], al1[1], al1[2], al1[3], ad + 16 * LAP * 2);
            }
            unsigned b0, b1;
            ldsm2(b0, b1, aB + ((wid * 8 + b_roff) * LAP + k0 + b_koff) * 2);

            mma16816h(acc0h, ah0, b0, b1);
            mma16816h(acc0l, al0, b0, b1);
            mma16816h(acc1h, ah1, b0, b1);
            mma16816h(acc1l, al1, b0, b1);
        }

        // pointwise in registers: i=row g, f=row g+8, g=row 16+g, o=row 24+g
        float i0 = sigf(acc0h[0] + acc0l[0] * LO_INV + xwi.x);
        float i1 = sigf(acc0h[1] + acc0l[1] * LO_INV + xwi.y);
        float f0 = sigf(acc0h[2] + acc0l[2] * LO_INV + xwf.x);
        float f1 = sigf(acc0h[3] + acc0l[3] * LO_INV + xwf.y);
        float gg0 = tanhfast(acc1h[0] + acc1l[0] * LO_INV + xwg.x);
        float gg1 = tanhfast(acc1h[1] + acc1l[1] * LO_INV + xwg.y);
        float o0 = sigf(acc1h[2] + acc1l[2] * LO_INV + xwo.x);
        float o1 = sigf(acc1h[3] + acc1l[3] * LO_INV + xwo.y);

        c0 = fminf(fmaxf(f0 * c0 + i0 * gg0, -100.f), 100.f);
        c1 = fminf(fmaxf(f1 * c1 + i1 * gg1, -100.f), 100.f);
        float h0 = o0 * tanhfast(c0);
        float h1 = o1 * tanhfast(c1);

        // fp32 layer output
        *(float2*)&outT[((size_t)dir * Hn + u0 + g) * Mtot + mo] = make_float2(h0, h1);

        // fp16 h for next step, layout [b][k=unit]
        {
            __half* wh = g_hbf + (((size_t)((s + 1) & 1) * 2 + dir) << 15);
            wh[(size_t)bb * 512 + u0 + g] = __float2half_rn(h0);
            wh[(size_t)(bb + 1) * 512 + u0 + g] = __float2half_rn(h1);
        }

        // per-direction grid barrier: release-arrive, acquire-poll
        if (s < Tn - 1) {
            __syncthreads();
            if (tid == 0) red_release(ctr);
            unsigned target = 64u * (unsigned)(s + 1);
            while (ldacq(ctr) < target) {}
        }
    }
}

// ===================== attention logits =====================
__global__ __launch_bounds__(512)
void attn_logit_kernel(const float* __restrict__ h1T, const float* __restrict__ Wa,
                       const float* __restrict__ ba, float* __restrict__ logit) {
    __shared__ float sWa[Hn];
    __shared__ float red[8][64];
    const int t = blockIdx.x;
    const int ug = threadIdx.x >> 6, b = threadIdx.x & 63;
    sWa[threadIdx.x] = Wa[threadIdx.x];
    __syncthreads();

    float acc = 0.f;
    const size_t moff = (size_t)t * Bn + b;
#pragma unroll 4
    for (int uu = 0; uu < 64; uu++) {
        int u = ug * 64 + uu;
        float hf = h1T[(size_t)u * Mtot + moff];
        float hb = h1T[((size_t)Hn + u) * Mtot + moff];
        acc += (hf + hb) * sWa[u];
    }
    red[ug][b] = acc;
    __syncthreads();
    if (ug == 0) {
        float s = ba[0];
#pragma unroll
        for (int g = 0; g < 8; g++) s += red[g][b];
        logit[t * Bn + b] = s;
    }
}

// ===================== softmax over t (CTA per b) =====================
__global__ __launch_bounds__(512)
void softmax_kernel(const float* __restrict__ logit, float* __restrict__ outp,
                    float* __restrict__ aT) {
    __shared__ float red[Tn];
    const int b = blockIdx.x, t = threadIdx.x;
    float v = logit[t * Bn + b];
    red[t] = v; __syncthreads();
    for (int st = 256; st > 0; st >>= 1) {
        if (t < st) red[t] = fmaxf(red[t], red[t + st]);
        __syncthreads();
    }
    float m = red[0]; __syncthreads();
    float e = expf(v - m);
    red[t] = e; __syncthreads();
    for (int st = 256; st > 0; st >>= 1) {
        if (t < st) red[t] += red[t + st];
        __syncthreads();
    }
    float a = e / red[0];
    outp[Bn * NOUT + b * Tn + t] = a;
    aT[t * Bn + b] = a;
}

// ===================== attention pooling (CTA per u) =====================
__global__ __launch_bounds__(64)
void pool_kernel(const float* __restrict__ h1T, const float* __restrict__ aT,
                 float* __restrict__ pooledT) {
    const int u = blockIdx.x, b = threadIdx.x;
    const float* hf = h1T + (size_t)u * Mtot;
    const float* hb = h1T + ((size_t)Hn + u) * Mtot;
    float acc = 0.f;
#pragma unroll 4
    for (int t = 0; t < Tn; t++) {
        acc += (hf[t * Bn + b] + hb[t * Bn + b]) * aT[t * Bn + b];
    }
    pooledT[u * Bn + b] = acc;
}

// ===================== output head (CTA per b) =====================
__global__ __launch_bounds__(128)
void pred_kernel(const float* __restrict__ pooledT, const float* __restrict__ Wo,
                 const float* __restrict__ bo, float* __restrict__ outp) {
    __shared__ float sp[Hn];
    const int b = blockIdx.x, o = threadIdx.x;
    for (int u = o; u < Hn; u += 128) sp[u] = pooledT[u * Bn + b];
    __syncthreads();
    float s = bo[o];
    const float* wp = Wo + (size_t)o * Hn;
#pragma unroll 4
    for (int u = 0; u < Hn; u++) s += sp[u] * wp[u];
    outp[b * NOUT + o] = s;
}

// ===================== launch =====================
extern "C" void kernel_launch(void* const* d_in, const int* in_sizes, int n_in,
                              void* d_out, int out_size) {
    (void)in_sizes; (void)n_in; (void)out_size;
    const float* input = (const float*)d_in[0];
    const float* Wih0  = (const float*)d_in[1];
    const float* Whh0  = (const float*)d_in[2];
    const float* b0    = (const float*)d_in[3];
    const float* Wih1  = (const float*)d_in[4];
    const float* Whh1  = (const float*)d_in[5];
    const float* b1    = (const float*)d_in[6];
    const float* Wa    = (const float*)d_in[7];
    const float* ba    = (const float*)d_in[8];
    const float* Wo    = (const float*)d_in[9];
    const float* bo    = (const float*)d_in[10];
    float* outp = (float*)d_out;

    float *xw, *out0, *out1, *logit, *aT, *pooledT;
    __nv_bfloat16 *xhi, *xlo, *whi, *wlo;
    cudaGetSymbolAddress((void**)&xw, g_xw);
    cudaGetSymbolAddress((void**)&out0, g_out0);
    cudaGetSymbolAddress((void**)&out1, g_out1);
    cudaGetSymbolAddress((void**)&logit, g_logit);
    cudaGetSymbolAddress((void**)&aT, g_attnT);
    cudaGetSymbolAddress((void**)&pooledT, g_pooledT);
    cudaGetSymbolAddress((void**)&xhi, g_xhi);
    cudaGetSymbolAddress((void**)&xlo, g_xlo);
    cudaGetSymbolAddress((void**)&whi, g_whi);
    cudaGetSymbolAddress((void**)&wlo, g_wlo);

    cudaFuncSetAttribute(lstm_mma_kernel, cudaFuncAttributeMaxDynamicSharedMemorySize,
                         LSTM2_SMEM);
    cudaFuncSetAttribute(mma_gemm_kernel, cudaFuncAttributeMaxDynamicSharedMemorySize,
                         GEMM_SMEM);

    dim3 mgrid(32, 256);   // 32 n-tiles (4096/128), 256 m-tiles

    // ---- layer 0 ----
    convert_split_kernel<<<2048, 256>>>(Wih0, whi, wlo, 2 * G4 * 256);
    convert_split_kernel<<<4096, 256>>>(input, xhi, xlo, Mtot * 256);
    mma_gemm_kernel<<<mgrid, 256, GEMM_SMEM>>>(whi, wlo, xhi, xlo, b0, xw, 256);
    init_kernel<<<64, 256>>>();
    lstm_mma_kernel<<<NCTA_LSTM, 256, LSTM2_SMEM>>>(xw, Whh0, out0);

    // ---- layer 1 ----
    convert_split_kernel<<<4096, 256>>>(Wih1, whi, wlo, 2 * G4 * 1024);
    transpose_split_kernel<<<dim3(1024, 32), dim3(32, 8)>>>(out0, xhi, xlo);
    mma_gemm_kernel<<<mgrid, 256, GEMM_SMEM>>>(whi, wlo, xhi, xlo, b1, xw, 1024);
    init_kernel<<<64, 256>>>();
    lstm_mma_kernel<<<NCTA_LSTM, 256, LSTM2_SMEM>>>(xw, Whh1, out1);

    // ---- attention + head ----
    attn_logit_kernel<<<Tn, 512>>>(out1, Wa, ba, logit);
    softmax_kernel<<<Bn, Tn>>>(logit, outp, aT);
    pool_kernel<<<Hn, Bn>>>(out1, aT, pooledT);
    pred_kernel<<<Bn, NOUT>>>(pooledT, Wo, bo, outp);
}

// round 12
// speedup vs baseline: 3.5375x; 1.1396x over previous
#include <cuda_runtime.h>
#include <cuda_bf16.h>
#include <cuda_fp16.h>
#include <cstdint>
#include <math.h>

#define Tn   512
#define Bn   64
#define Hn   512
#define G4   2048
#define NOUT 128
#define Mtot (Tn * Bn)          // 32768
#define NCTA_LSTM 128

// ---------------- scratch ----------------
__device__ float g_xw[(size_t)2 * G4 * Mtot];        // xw_T[dir][n][m]
__device__ float g_out0[(size_t)2 * Hn * Mtot];      // out0_T[dir][u][m]
__device__ float g_out1[(size_t)2 * Hn * Mtot];      // out1_T[dir][u][m]
__device__ float g_logit[Tn * Bn];
__device__ float g_attnT[Tn * Bn];
__device__ float g_pooledT[Hn * Bn];
__device__ unsigned g_barv[64];
// h exchange buffers: [buf2][dir2][b64][k512] fp16
__device__ __half g_hbf[2 * 2 * 64 * 512];
// bf16 split buffers for the big GEMM
__device__ __nv_bfloat16 g_xhi[(size_t)Mtot * 1024];
__device__ __nv_bfloat16 g_xlo[(size_t)Mtot * 1024];
__device__ __nv_bfloat16 g_whi[2 * G4 * 1024];
__device__ __nv_bfloat16 g_wlo[2 * G4 * 1024];

__device__ __forceinline__ unsigned ldacq(const unsigned* p) {
    unsigned v;
    asm volatile("ld.acquire.gpu.global.b32 %0, [%1];" : "=r"(v) : "l"(p) : "memory");
    return v;
}
__device__ __forceinline__ void red_release(unsigned* p) {
    asm volatile("red.release.gpu.global.add.u32 [%0], %1;" :: "l"(p), "r"(1u) : "memory");
}
__device__ __forceinline__ float sigf(float x) {
    return 1.f / (1.f + __expf(-x));
}
__device__ __forceinline__ float tanhfast(float x) {
    return 1.f - 2.f / (1.f + __expf(2.f * x));
}

// ==================== mma.sync helpers ====================
__device__ __forceinline__ unsigned smem_u32(const void* p) {
    unsigned a;
    asm("{ .reg .u64 t; cvta.to.shared.u64 t, %1; cvt.u32.u64 %0, t; }" : "=r"(a) : "l"(p));
    return a;
}
__device__ __forceinline__ void ldsm4(unsigned& r0, unsigned& r1, unsigned& r2, unsigned& r3,
                                      unsigned addr) {
    asm volatile("ldmatrix.sync.aligned.m8n8.x4.shared.b16 {%0,%1,%2,%3}, [%4];"
                 : "=r"(r0), "=r"(r1), "=r"(r2), "=r"(r3) : "r"(addr));
}
__device__ __forceinline__ void ldsm2(unsigned& r0, unsigned& r1, unsigned addr) {
    asm volatile("ldmatrix.sync.aligned.m8n8.x2.shared.b16 {%0,%1}, [%2];"
                 : "=r"(r0), "=r"(r1) : "r"(addr));
}
__device__ __forceinline__ void mma16816(float* c, const unsigned* a, unsigned b0, unsigned b1) {
    asm volatile(
        "mma.sync.aligned.m16n8k16.row.col.f32.bf16.bf16.f32 "
        "{%0,%1,%2,%3}, {%4,%5,%6,%7}, {%8,%9}, {%0,%1,%2,%3};"
        : "+f"(c[0]), "+f"(c[1]), "+f"(c[2]), "+f"(c[3])
        : "r"(a[0]), "r"(a[1]), "r"(a[2]), "r"(a[3]), "r"(b0), "r"(b1));
}
__device__ __forceinline__ void mma16816h(float* c, const unsigned* a, unsigned b0, unsigned b1) {
    asm volatile(
        "mma.sync.aligned.m16n8k16.row.col.f32.f16.f16.f32 "
        "{%0,%1,%2,%3}, {%4,%5,%6,%7}, {%8,%9}, {%0,%1,%2,%3};"
        : "+f"(c[0]), "+f"(c[1]), "+f"(c[2]), "+f"(c[3])
        : "r"(a[0]), "r"(a[1]), "r"(a[2]), "r"(a[3]), "r"(b0), "r"(b1));
}
__device__ __forceinline__ void cpasync16(unsigned dst, const void* src) {
    asm volatile("cp.async.cg.shared.global [%0], [%1], 16;" :: "r"(dst), "l"(src));
}
__device__ __forceinline__ void cpasync_commit() {
    asm volatile("cp.async.commit_group;" ::: "memory");
}
__device__ __forceinline__ void cpasync_wait0() {
    asm volatile("cp.async.wait_group 0;" ::: "memory");
}

// ==================== fp32 -> bf16 hi/lo converters ====================
__global__ void convert_split_kernel(const float* __restrict__ in,
                                     __nv_bfloat16* __restrict__ hi,
                                     __nv_bfloat16* __restrict__ lo, int n) {
    int i = blockIdx.x * blockDim.x + threadIdx.x;
    for (; i < n; i += gridDim.x * blockDim.x) {
        float v = in[i];
        __nv_bfloat16 h = __float2bfloat16_rn(v);
        hi[i] = h;
        lo[i] = __float2bfloat16_rn(v - __bfloat162float(h));
    }
}

// transpose-convert: in[k][m] fp32 (k=1024, m=32768) -> hi/lo[m][k]
__global__ __launch_bounds__(256)
void transpose_split_kernel(const float* __restrict__ in,
                            __nv_bfloat16* __restrict__ hi,
                            __nv_bfloat16* __restrict__ lo) {
    __shared__ float s[32][33];
    const int m0 = blockIdx.x * 32, k0 = blockIdx.y * 32;
    const int tx = threadIdx.x, ty = threadIdx.y;  // 32 x 8
#pragma unroll
    for (int j = 0; j < 4; j++)
        s[ty + 8 * j][tx] = in[(size_t)(k0 + ty + 8 * j) * Mtot + m0 + tx];
    __syncthreads();
#pragma unroll
    for (int j = 0; j < 4; j++) {
        float v = s[tx][ty + 8 * j];
        __nv_bfloat16 h = __float2bfloat16_rn(v);
        size_t o = (size_t)(m0 + ty + 8 * j) * 1024 + k0 + tx;
        hi[o] = h;
        lo[o] = __float2bfloat16_rn(v - __bfloat162float(h));
    }
}

// ==================== mma.sync GEMM (proven, unchanged) ====================
#define GP      72
#define GTILE   (128 * GP * 2)
#define GBUF    (4 * GTILE)
#define GEMM_SMEM (2 * GBUF)

__global__ __launch_bounds__(256, 1)
void mma_gemm_kernel(const __nv_bfloat16* __restrict__ Whi, const __nv_bfloat16* __restrict__ Wlo,
                     const __nv_bfloat16* __restrict__ Xhi, const __nv_bfloat16* __restrict__ Xlo,
                     const float* __restrict__ bias, float* __restrict__ C, int K) {
    extern __shared__ char smem[];
    const unsigned sb = smem_u32(smem);
    const int tid = threadIdx.x;
    const int wid = tid >> 5, lane = tid & 31;
    const int wa = wid & 3;
    const int wb = wid >> 2;
    const int n0 = blockIdx.x * 128;
    const int m0 = blockIdx.y * 128;
    const int NC = K >> 6;

    const __nv_bfloat16* gsrc[4] = {Whi + (size_t)n0 * K, Wlo + (size_t)n0 * K,
                                    Xhi + (size_t)m0 * K, Xlo + (size_t)m0 * K};

    float acc[2][8][4];
#pragma unroll
    for (int i = 0; i < 2; i++)
#pragma unroll
        for (int j = 0; j < 8; j++)
#pragma unroll
            for (int q = 0; q < 4; q++) acc[i][j][q] = 0.f;

#pragma unroll
    for (int tgt = 0; tgt < 4; tgt++) {
#pragma unroll
        for (int i = 0; i < 4; i++) {
            int lin = tid + i * 256;
            int row = lin >> 3, unit = lin & 7;
            cpasync16(sb + tgt * GTILE + (row * GP + unit * 8) * 2,
                      gsrc[tgt] + (size_t)row * K + unit * 8);
        }
    }
    cpasync_commit();

    const int a_roff = (lane & 7) + ((lane >> 3) & 1) * 8;
    const int a_koff = ((lane >> 4) & 1) * 8;
    const int b_roff = (lane & 7) + ((lane >> 4) & 1) * 8;
    const int b_koff = ((lane >> 3) & 1) * 8;

#pragma unroll 1
    for (int c = 0; c < NC; c++) {
        cpasync_wait0();
        __syncthreads();
        if (c + 1 < NC) {
            const int kc = (c + 1) * 64;
            const unsigned bo = ((c + 1) & 1) * GBUF;
#pragma unroll
            for (int tgt = 0; tgt < 4; tgt++) {
#pragma unroll
                for (int i = 0; i < 4; i++) {
                    int lin = tid + i * 256;
                    int row = lin >> 3, unit = lin & 7;
                    cpasync16(sb + bo + tgt * GTILE + (row * GP + unit * 8) * 2,
                              gsrc[tgt] + (size_t)row * K + kc + unit * 8);
                }
            }
            cpasync_commit();
        }
        const unsigned cb = (c & 1) * GBUF;
#pragma unroll
        for (int ks = 0; ks < 4; ks++) {
            const int k0 = ks * 16;
            unsigned ahi[2][4], alo[2][4], bhi[4][4], blo[4][4];
#pragma unroll
            for (int mf = 0; mf < 2; mf++) {
                int row = wa * 32 + mf * 16 + a_roff;
                unsigned ad = sb + cb + (row * GP + k0 + a_koff) * 2;
                ldsm4(ahi[mf][0], ahi[mf][1], ahi[mf][2], ahi[mf][3], ad);
                ldsm4(alo[mf][0], alo[mf][1], alo[mf][2], alo[mf][3], ad + GTILE);
            }
#pragma unroll
            for (int nf = 0; nf < 4; nf++) {
                int row = wb * 64 + nf * 16 + b_roff;
                unsigned ad = sb + cb + 2 * GTILE + (row * GP + k0 + b_koff) * 2;
                ldsm4(bhi[nf][0], bhi[nf][1], bhi[nf][2], bhi[nf][3], ad);
                ldsm4(blo[nf][0], blo[nf][1], blo[nf][2], blo[nf][3], ad + GTILE);
            }
#pragma unroll
            for (int mf = 0; mf < 2; mf++)
#pragma unroll
                for (int nf = 0; nf < 4; nf++)
#pragma unroll
                    for (int hf = 0; hf < 2; hf++) {
                        float* cc = acc[mf][nf * 2 + hf];
                        mma16816(cc, ahi[mf], bhi[nf][hf * 2], bhi[nf][hf * 2 + 1]);
                        mma16816(cc, ahi[mf], blo[nf][hf * 2], blo[nf][hf * 2 + 1]);
                        mma16816(cc, alo[mf], bhi[nf][hf * 2], bhi[nf][hf * 2 + 1]);
                    }
        }
        __syncthreads();
    }

    const int g = lane >> 2, tig = lane & 3;
#pragma unroll
    for (int mf = 0; mf < 2; mf++) {
        const int nr = n0 + wa * 32 + mf * 16 + g;
        const float bv0 = bias[nr];
        const float bv1 = bias[nr + 8];
#pragma unroll
        for (int j = 0; j < 8; j++) {
            const int mcol = m0 + wb * 64 + j * 8 + tig * 2;
            float2 v0 = make_float2(acc[mf][j][0] + bv0, acc[mf][j][1] + bv0);
            float2 v1 = make_float2(acc[mf][j][2] + bv1, acc[mf][j][3] + bv1);
            *(float2*)&C[(size_t)nr * Mtot + mcol] = v0;
            *(float2*)&C[(size_t)(nr + 8) * Mtot + mcol] = v1;
        }
    }
}

// ===================== init: zero h fp16 buffers + barrier counters =====================
__global__ void init_kernel() {
    int i = blockIdx.x * blockDim.x + threadIdx.x;
    if (i < 64) g_barv[i] = 0u;
    uint4* p = (uint4*)g_hbf;
    const int n = (2 * 2 * 64 * 512) / 8;   // uint4 = 8 halves
    for (int j = i; j < n; j += gridDim.x * blockDim.x)
        p[j] = make_uint4(0u, 0u, 0u, 0u);
}

// ===================== tensor-core persistent LSTM layer (fp16 hi-only W) =====================
// CTA = (dir, 8 units) -> 32 gate rows. Warp w owns batches w*8..w*8+7.
// gates[32][64] = Whi_fp16[32][512] @ h_fp16[512][64], fp32 accum.
#define LAP 520
#define LSTM2_SMEM ((32 * LAP + 64 * LAP) * 2)   // 99840 B

__global__ __launch_bounds__(256, 1)
void lstm_mma_kernel(const float* __restrict__ xwT, const float* __restrict__ Whh,
                     float* __restrict__ outT) {
    extern __shared__ __half hbuf[];
    __half* sAhi = hbuf;                    // [32][520]
    __half* sB   = sAhi + 32 * LAP;         // [64][520]

    const int tid = threadIdx.x;
    const int wid = tid >> 5, lane = tid & 31;
    const int dir = blockIdx.x >> 6;
    const int u0 = (blockIdx.x & 63) << 3;

    // load Whh slice into smem as fp16 (hi only)
    for (int i = tid; i < 32 * 512; i += 256) {
        int r = i >> 9, k = i & 511;
        int gate = r >> 3, ul = r & 7;
        float w = Whh[((size_t)dir * G4 + gate * Hn + u0 + ul) * Hn + k];
        sAhi[r * LAP + k] = __float2half_rn(w);
    }

    const unsigned aAhi = smem_u32(sAhi);
    const unsigned aB   = smem_u32(sB);

    const int a_roff = (lane & 7) + ((lane >> 3) & 1) * 8;
    const int a_koff = ((lane >> 4) & 1) * 8;
    const int b_roff = lane & 7;
    const int b_koff = ((lane >> 3) & 1) * 8;

    const int g = lane >> 2;             // unit-local; acc rows {g,g+8,g+16,g+24}
    const int tig = lane & 3;
    const int bb = wid * 8 + tig * 2;    // first of this thread's 2 batches

    float c0 = 0.f, c1 = 0.f;            // cell state in registers
    unsigned* ctr = &g_barv[dir * 32];
    const size_t xrow = (size_t)dir * G4 + u0 + g;

#pragma unroll 1
    for (int s = 0; s < Tn; s++) {
        const int t = dir ? (Tn - 1 - s) : s;
        const size_t mo = (size_t)t * Bn + bb;

        // stage h(s) fp16 into smem [b][k]: 64 rows x 512 cols = 4096 x 8-half lines
        {
            const __half* gh = g_hbf + (((size_t)(s & 1) * 2 + dir) << 15);
#pragma unroll
            for (int it = 0; it < 16; it++) {
                int i = tid + it * 256;
                int b = i >> 6, j = (i & 63) * 8;
                cpasync16(aB + (b * LAP + j) * 2, gh + b * 512 + j);
            }
            cpasync_commit();
        }

        // xw for all 4 gates (fp32 exact) — overlaps cp.async flight
        float2 xwi = __ldg((const float2*)&xwT[(xrow + 0 * Hn) * Mtot + mo]);
        float2 xwf = __ldg((const float2*)&xwT[(xrow + 1 * Hn) * Mtot + mo]);
        float2 xwg = __ldg((const float2*)&xwT[(xrow + 2 * Hn) * Mtot + mo]);
        float2 xwo = __ldg((const float2*)&xwT[(xrow + 3 * Hn) * Mtot + mo]);

        cpasync_wait0();
        __syncthreads();

        float acc0[4] = {0.f, 0.f, 0.f, 0.f};  // rows g(i), g+8(f)
        float acc1[4] = {0.f, 0.f, 0.f, 0.f};  // rows 16+g(g), 24+g(o)

#pragma unroll 8
        for (int ks = 0; ks < 32; ks++) {
            const int k0 = ks * 16;
            unsigned ah0[4], ah1[4];
            unsigned ad = aAhi + ((a_roff) * LAP + k0 + a_koff) * 2;
            ldsm4(ah0[0], ah0[1], ah0[2], ah0[3], ad);
            ldsm4(ah1[0], ah1[1], ah1[2], ah1[3], ad + 16 * LAP * 2);
            unsigned b0, b1;
            ldsm2(b0, b1, aB + ((wid * 8 + b_roff) * LAP + k0 + b_koff) * 2);

            mma16816h(acc0, ah0, b0, b1);
            mma16816h(acc1, ah1, b0, b1);
        }

        // pointwise in registers: i=row g, f=row g+8, g=row 16+g, o=row 24+g
        float i0 = sigf(acc0[0] + xwi.x);
        float i1 = sigf(acc0[1] + xwi.y);
        float f0 = sigf(acc0[2] + xwf.x);
        float f1 = sigf(acc0[3] + xwf.y);
        float gg0 = tanhfast(acc1[0] + xwg.x);
        float gg1 = tanhfast(acc1[1] + xwg.y);
        float o0 = sigf(acc1[2] + xwo.x);
        float o1 = sigf(acc1[3] + xwo.y);

        c0 = fminf(fmaxf(f0 * c0 + i0 * gg0, -100.f), 100.f);
        c1 = fminf(fmaxf(f1 * c1 + i1 * gg1, -100.f), 100.f);
        float h0 = o0 * tanhfast(c0);
        float h1 = o1 * tanhfast(c1);

        // fp32 layer output
        *(float2*)&outT[((size_t)dir * Hn + u0 + g) * Mtot + mo] = make_float2(h0, h1);

        // fp16 h for next step, layout [b][k=unit]
        {
            __half* wh = g_hbf + (((size_t)((s + 1) & 1) * 2 + dir) << 15);
            wh[(size_t)bb * 512 + u0 + g] = __float2half_rn(h0);
            wh[(size_t)(bb + 1) * 512 + u0 + g] = __float2half_rn(h1);
        }

        // per-direction grid barrier: release-arrive by tid0, tid0 polls, CTA syncs
        if (s < Tn - 1) {
            __syncthreads();
            if (tid == 0) {
                red_release(ctr);
                unsigned target = 64u * (unsigned)(s + 1);
                while (ldacq(ctr) < target) {}
            }
            __syncthreads();
        }
    }
}

// ===================== attention logits =====================
__global__ __launch_bounds__(512)
void attn_logit_kernel(const float* __restrict__ h1T, const float* __restrict__ Wa,
                       const float* __restrict__ ba, float* __restrict__ logit) {
    __shared__ float sWa[Hn];
    __shared__ float red[8][64];
    const int t = blockIdx.x;
    const int ug = threadIdx.x >> 6, b = threadIdx.x & 63;
    sWa[threadIdx.x] = Wa[threadIdx.x];
    __syncthreads();

    float acc = 0.f;
    const size_t moff = (size_t)t * Bn + b;
#pragma unroll 4
    for (int uu = 0; uu < 64; uu++) {
        int u = ug * 64 + uu;
        float hf = h1T[(size_t)u * Mtot + moff];
        float hb = h1T[((size_t)Hn + u) * Mtot + moff];
        acc += (hf + hb) * sWa[u];
    }
    red[ug][b] = acc;
    __syncthreads();
    if (ug == 0) {
        float s = ba[0];
#pragma unroll
        for (int g = 0; g < 8; g++) s += red[g][b];
        logit[t * Bn + b] = s;
    }
}

// ===================== softmax over t (CTA per b) =====================
__global__ __launch_bounds__(512)
void softmax_kernel(const float* __restrict__ logit, float* __restrict__ outp,
                    float* __restrict__ aT) {
    __shared__ float red[Tn];
    const int b = blockIdx.x, t = threadIdx.x;
    float v = logit[t * Bn + b];
    red[t] = v; __syncthreads();
    for (int st = 256; st > 0; st >>= 1) {
        if (t < st) red[t] = fmaxf(red[t], red[t + st]);
        __syncthreads();
    }
    float m = red[0]; __syncthreads();
    float e = expf(v - m);
    red[t] = e; __syncthreads();
    for (int st = 256; st > 0; st >>= 1) {
        if (t < st) red[t] += red[t + st];
        __syncthreads();
    }
    float a = e / red[0];
    outp[Bn * NOUT + b * Tn + t] = a;
    aT[t * Bn + b] = a;
}

// ===================== attention pooling (CTA per u) =====================
__global__ __launch_bounds__(64)
void pool_kernel(const float* __restrict__ h1T, const float* __restrict__ aT,
                 float* __restrict__ pooledT) {
    const int u = blockIdx.x, b = threadIdx.x;
    const float* hf = h1T + (size_t)u * Mtot;
    const float* hb = h1T + ((size_t)Hn + u) * Mtot;
    float acc = 0.f;
#pragma unroll 4
    for (int t = 0; t < Tn; t++) {
        acc += (hf[t * Bn + b] + hb[t * Bn + b]) * aT[t * Bn + b];
    }
    pooledT[u * Bn + b] = acc;
}

// ===================== output head (CTA per b) =====================
__global__ __launch_bounds__(128)
void pred_kernel(const float* __restrict__ pooledT, const float* __restrict__ Wo,
                 const float* __restrict__ bo, float* __restrict__ outp) {
    __shared__ float sp[Hn];
    const int b = blockIdx.x, o = threadIdx.x;
    for (int u = o; u < Hn; u += 128) sp[u] = pooledT[u * Bn + b];
    __syncthreads();
    float s = bo[o];
    const float* wp = Wo + (size_t)o * Hn;
#pragma unroll 4
    for (int u = 0; u < Hn; u++) s += sp[u] * wp[u];
    outp[b * NOUT + o] = s;
}

// ===================== launch =====================
extern "C" void kernel_launch(void* const* d_in, const int* in_sizes, int n_in,
                              void* d_out, int out_size) {
    (void)in_sizes; (void)n_in; (void)out_size;
    const float* input = (const float*)d_in[0];
    const float* Wih0  = (const float*)d_in[1];
    const float* Whh0  = (const float*)d_in[2];
    const float* b0    = (const float*)d_in[3];
    const float* Wih1  = (const float*)d_in[4];
    const float* Whh1  = (const float*)d_in[5];
    const float* b1    = (const float*)d_in[6];
    const float* Wa    = (const float*)d_in[7];
    const float* ba    = (const float*)d_in[8];
    const float* Wo    = (const float*)d_in[9];
    const float* bo    = (const float*)d_in[10];
    float* outp = (float*)d_out;

    float *xw, *out0, *out1, *logit, *aT, *pooledT;
    __nv_bfloat16 *xhi, *xlo, *whi, *wlo;
    cudaGetSymbolAddress((void**)&xw, g_xw);
    cudaGetSymbolAddress((void**)&out0, g_out0);
    cudaGetSymbolAddress((void**)&out1, g_out1);
    cudaGetSymbolAddress((void**)&logit, g_logit);
    cudaGetSymbolAddress((void**)&aT, g_attnT);
    cudaGetSymbolAddress((void**)&pooledT, g_pooledT);
    cudaGetSymbolAddress((void**)&xhi, g_xhi);
    cudaGetSymbolAddress((void**)&xlo, g_xlo);
    cudaGetSymbolAddress((void**)&whi, g_whi);
    cudaGetSymbolAddress((void**)&wlo, g_wlo);

    cudaFuncSetAttribute(lstm_mma_kernel, cudaFuncAttributeMaxDynamicSharedMemorySize,
                         LSTM2_SMEM);
    cudaFuncSetAttribute(mma_gemm_kernel, cudaFuncAttributeMaxDynamicSharedMemorySize,
                         GEMM_SMEM);

    dim3 mgrid(32, 256);   // 32 n-tiles (4096/128), 256 m-tiles

    // ---- layer 0 ----
    convert_split_kernel<<<2048, 256>>>(Wih0, whi, wlo, 2 * G4 * 256);
    convert_split_kernel<<<4096, 256>>>(input, xhi, xlo, Mtot * 256);
    mma_gemm_kernel<<<mgrid, 256, GEMM_SMEM>>>(whi, wlo, xhi, xlo, b0, xw, 256);
    init_kernel<<<64, 256>>>();
    lstm_mma_kernel<<<NCTA_LSTM, 256, LSTM2_SMEM>>>(xw, Whh0, out0);

    // ---- layer 1 ----
    convert_split_kernel<<<4096, 256>>>(Wih1, whi, wlo, 2 * G4 * 1024);
    transpose_split_kernel<<<dim3(1024, 32), dim3(32, 8)>>>(out0, xhi, xlo);
    mma_gemm_kernel<<<mgrid, 256, GEMM_SMEM>>>(whi, wlo, xhi, xlo, b1, xw, 1024);
    init_kernel<<<64, 256>>>();
    lstm_mma_kernel<<<NCTA_LSTM, 256, LSTM2_SMEM>>>(xw, Whh1, out1);

    // ---- attention + head ----
    attn_logit_kernel<<<Tn, 512>>>(out1, Wa, ba, logit);
    softmax_kernel<<<Bn, Tn>>>(logit, outp, aT);
    pool_kernel<<<Hn, Bn>>>(out1, aT, pooledT);
    pred_kernel<<<Bn, NOUT>>>(pooledT, Wo, bo, outp);
}

// round 13
// speedup vs baseline: 4.5535x; 1.2872x over previous
#include <cuda_runtime.h>
#include <cuda_bf16.h>
#include <cuda_fp16.h>
#include <cstdint>
#include <math.h>

#define Tn   512
#define Bn   64
#define Hn   512
#define G4   2048
#define NOUT 128
#define Mtot (Tn * Bn)          // 32768
#define NCTA_LSTM 128

// ---------------- scratch ----------------
__device__ float g_xw[(size_t)2 * G4 * Mtot];        // xw_T[dir][n][m]
__device__ float g_out0[(size_t)2 * Hn * Mtot];      // out0_T[dir][u][m]
__device__ float g_out1[(size_t)2 * Hn * Mtot];      // out1_T[dir][u][m]
__device__ float g_logit[Tn * Bn];
__device__ float g_attnT[Tn * Bn];
__device__ float g_pooledT[Hn * Bn];
__device__ unsigned g_barv[64];
// h exchange buffers: [buf2][dir2][b64][k512] fp16
__device__ __half g_hbf[2 * 2 * 64 * 512];
// fp16 buffers for the big GEMM
__device__ __half g_xh[(size_t)Mtot * 1024];
__device__ __half g_wh[2 * G4 * 1024];

__device__ __forceinline__ unsigned ldacq(const unsigned* p) {
    unsigned v;
    asm volatile("ld.acquire.gpu.global.b32 %0, [%1];" : "=r"(v) : "l"(p) : "memory");
    return v;
}
__device__ __forceinline__ void red_release(unsigned* p) {
    asm volatile("red.release.gpu.global.add.u32 [%0], %1;" :: "l"(p), "r"(1u) : "memory");
}
__device__ __forceinline__ float sigf(float x) {
    return 1.f / (1.f + __expf(-x));
}
__device__ __forceinline__ float tanhfast(float x) {
    return 1.f - 2.f / (1.f + __expf(2.f * x));
}

// ==================== mma.sync helpers ====================
__device__ __forceinline__ unsigned smem_u32(const void* p) {
    unsigned a;
    asm("{ .reg .u64 t; cvta.to.shared.u64 t, %1; cvt.u32.u64 %0, t; }" : "=r"(a) : "l"(p));
    return a;
}
__device__ __forceinline__ void ldsm4(unsigned& r0, unsigned& r1, unsigned& r2, unsigned& r3,
                                      unsigned addr) {
    asm volatile("ldmatrix.sync.aligned.m8n8.x4.shared.b16 {%0,%1,%2,%3}, [%4];"
                 : "=r"(r0), "=r"(r1), "=r"(r2), "=r"(r3) : "r"(addr));
}
__device__ __forceinline__ void ldsm2(unsigned& r0, unsigned& r1, unsigned addr) {
    asm volatile("ldmatrix.sync.aligned.m8n8.x2.shared.b16 {%0,%1}, [%2];"
                 : "=r"(r0), "=r"(r1) : "r"(addr));
}
__device__ __forceinline__ void mma16816h(float* c, const unsigned* a, unsigned b0, unsigned b1) {
    asm volatile(
        "mma.sync.aligned.m16n8k16.row.col.f32.f16.f16.f32 "
        "{%0,%1,%2,%3}, {%4,%5,%6,%7}, {%8,%9}, {%0,%1,%2,%3};"
        : "+f"(c[0]), "+f"(c[1]), "+f"(c[2]), "+f"(c[3])
        : "r"(a[0]), "r"(a[1]), "r"(a[2]), "r"(a[3]), "r"(b0), "r"(b1));
}
__device__ __forceinline__ void cpasync16(unsigned dst, const void* src) {
    asm volatile("cp.async.cg.shared.global [%0], [%1], 16;" :: "r"(dst), "l"(src));
}
__device__ __forceinline__ void cpasync_commit() {
    asm volatile("cp.async.commit_group;" ::: "memory");
}
__device__ __forceinline__ void cpasync_wait0() {
    asm volatile("cp.async.wait_group 0;" ::: "memory");
}

// ==================== fp32 -> fp16 converters ====================
__global__ void convert_f16_kernel(const float* __restrict__ in,
                                   __half* __restrict__ out, int n) {
    int i = blockIdx.x * blockDim.x + threadIdx.x;
    for (; i < n; i += gridDim.x * blockDim.x)
        out[i] = __float2half_rn(in[i]);
}

// transpose-convert: in[k][m] fp32 (k=1024, m=32768) -> out[m][k] fp16
__global__ __launch_bounds__(256)
void transpose_f16_kernel(const float* __restrict__ in, __half* __restrict__ out) {
    __shared__ float s[32][33];
    const int m0 = blockIdx.x * 32, k0 = blockIdx.y * 32;
    const int tx = threadIdx.x, ty = threadIdx.y;  // 32 x 8
#pragma unroll
    for (int j = 0; j < 4; j++)
        s[ty + 8 * j][tx] = in[(size_t)(k0 + ty + 8 * j) * Mtot + m0 + tx];
    __syncthreads();
#pragma unroll
    for (int j = 0; j < 4; j++)
        out[(size_t)(m0 + ty + 8 * j) * 1024 + k0 + tx] = __float2half_rn(s[tx][ty + 8 * j]);
}

// ==================== fp16 mma.sync GEMM ====================
// C[n][m] = sum_k W[n][k] * X[m][k] + bias[n], fp16 inputs, fp32 accum.
// n flattened over [2*G4]. CTA tile 128n x 128m, K chunks of 64, double-buffered.
#define GP      72
#define GTILE   (128 * GP * 2)          // 18432 B
#define GBUF    (2 * GTILE)             // W, X      (36864)
#define GEMM_SMEM (2 * GBUF)            // double buffer (73728)

__global__ __launch_bounds__(256, 2)
void mma_gemm_kernel(const __half* __restrict__ Wh, const __half* __restrict__ Xh,
                     const float* __restrict__ bias, float* __restrict__ C, int K) {
    extern __shared__ char smem[];
    const unsigned sb = smem_u32(smem);
    const int tid = threadIdx.x;
    const int wid = tid >> 5, lane = tid & 31;
    const int wa = wid & 3;
    const int wb = wid >> 2;
    const int n0 = blockIdx.x * 128;
    const int m0 = blockIdx.y * 128;
    const int NC = K >> 6;

    const __half* gsrc[2] = {Wh + (size_t)n0 * K, Xh + (size_t)m0 * K};

    float acc[2][8][4];
#pragma unroll
    for (int i = 0; i < 2; i++)
#pragma unroll
        for (int j = 0; j < 8; j++)
#pragma unroll
            for (int q = 0; q < 4; q++) acc[i][j][q] = 0.f;

#pragma unroll
    for (int tgt = 0; tgt < 2; tgt++) {
#pragma unroll
        for (int i = 0; i < 4; i++) {
            int lin = tid + i * 256;
            int row = lin >> 3, unit = lin & 7;
            cpasync16(sb + tgt * GTILE + (row * GP + unit * 8) * 2,
                      gsrc[tgt] + (size_t)row * K + unit * 8);
        }
    }
    cpasync_commit();

    const int a_roff = (lane & 7) + ((lane >> 3) & 1) * 8;
    const int a_koff = ((lane >> 4) & 1) * 8;
    const int b_roff = (lane & 7) + ((lane >> 4) & 1) * 8;
    const int b_koff = ((lane >> 3) & 1) * 8;

#pragma unroll 1
    for (int c = 0; c < NC; c++) {
        cpasync_wait0();
        __syncthreads();
        if (c + 1 < NC) {
            const int kc = (c + 1) * 64;
            const unsigned bo = ((c + 1) & 1) * GBUF;
#pragma unroll
            for (int tgt = 0; tgt < 2; tgt++) {
#pragma unroll
                for (int i = 0; i < 4; i++) {
                    int lin = tid + i * 256;
                    int row = lin >> 3, unit = lin & 7;
                    cpasync16(sb + bo + tgt * GTILE + (row * GP + unit * 8) * 2,
                              gsrc[tgt] + (size_t)row * K + kc + unit * 8);
                }
            }
            cpasync_commit();
        }
        const unsigned cb = (c & 1) * GBUF;
#pragma unroll
        for (int ks = 0; ks < 4; ks++) {
            const int k0 = ks * 16;
            unsigned af[2][4], bf[4][4];
#pragma unroll
            for (int mf = 0; mf < 2; mf++) {
                int row = wa * 32 + mf * 16 + a_roff;
                ldsm4(af[mf][0], af[mf][1], af[mf][2], af[mf][3],
                      sb + cb + (row * GP + k0 + a_koff) * 2);
            }
#pragma unroll
            for (int nf = 0; nf < 4; nf++) {
                int row = wb * 64 + nf * 16 + b_roff;
                ldsm4(bf[nf][0], bf[nf][1], bf[nf][2], bf[nf][3],
                      sb + cb + GTILE + (row * GP + k0 + b_koff) * 2);
            }
#pragma unroll
            for (int mf = 0; mf < 2; mf++)
#pragma unroll
                for (int nf = 0; nf < 4; nf++)
#pragma unroll
                    for (int hf = 0; hf < 2; hf++)
                        mma16816h(acc[mf][nf * 2 + hf], af[mf],
                                  bf[nf][hf * 2], bf[nf][hf * 2 + 1]);
        }
        __syncthreads();
    }

    const int g = lane >> 2, tig = lane & 3;
#pragma unroll
    for (int mf = 0; mf < 2; mf++) {
        const int nr = n0 + wa * 32 + mf * 16 + g;
        const float bv0 = bias[nr];
        const float bv1 = bias[nr + 8];
#pragma unroll
        for (int j = 0; j < 8; j++) {
            const int mcol = m0 + wb * 64 + j * 8 + tig * 2;
            float2 v0 = make_float2(acc[mf][j][0] + bv0, acc[mf][j][1] + bv0);
            float2 v1 = make_float2(acc[mf][j][2] + bv1, acc[mf][j][3] + bv1);
            *(float2*)&C[(size_t)nr * Mtot + mcol] = v0;
            *(float2*)&C[(size_t)(nr + 8) * Mtot + mcol] = v1;
        }
    }
}

// ===================== init: zero h fp16 buffers + barrier counters =====================
__global__ void init_kernel() {
    int i = blockIdx.x * blockDim.x + threadIdx.x;
    if (i < 64) g_barv[i] = 0u;
    uint4* p = (uint4*)g_hbf;
    const int n = (2 * 2 * 64 * 512) / 8;
    for (int j = i; j < n; j += gridDim.x * blockDim.x)
        p[j] = make_uint4(0u, 0u, 0u, 0u);
}

// ===================== tensor-core persistent LSTM layer (fp16 hi-only W) =====================
#define LAP 520
#define LSTM2_SMEM ((32 * LAP + 64 * LAP) * 2)   // 99840 B

__global__ __launch_bounds__(256, 1)
void lstm_mma_kernel(const float* __restrict__ xwT, const float* __restrict__ Whh,
                     float* __restrict__ outT) {
    extern __shared__ __half hbuf[];
    __half* sAhi = hbuf;                    // [32][520]
    __half* sB   = sAhi + 32 * LAP;         // [64][520]

    const int tid = threadIdx.x;
    const int wid = tid >> 5, lane = tid & 31;
    const int dir = blockIdx.x >> 6;
    const int u0 = (blockIdx.x & 63) << 3;

    for (int i = tid; i < 32 * 512; i += 256) {
        int r = i >> 9, k = i & 511;
        int gate = r >> 3, ul = r & 7;
        float w = Whh[((size_t)dir * G4 + gate * Hn + u0 + ul) * Hn + k];
        sAhi[r * LAP + k] = __float2half_rn(w);
    }

    const unsigned aAhi = smem_u32(sAhi);
    const unsigned aB   = smem_u32(sB);

    const int a_roff = (lane & 7) + ((lane >> 3) & 1) * 8;
    const int a_koff = ((lane >> 4) & 1) * 8;
    const int b_roff = lane & 7;
    const int b_koff = ((lane >> 3) & 1) * 8;

    const int g = lane >> 2;             // unit-local; acc rows {g,g+8,g+16,g+24}
    const int tig = lane & 3;
    const int bb = wid * 8 + tig * 2;    // first of this thread's 2 batches

    float c0 = 0.f, c1 = 0.f;
    unsigned* ctr = &g_barv[dir * 32];
    const size_t xrow = (size_t)dir * G4 + u0 + g;

#pragma unroll 1
    for (int s = 0; s < Tn; s++) {
        const int t = dir ? (Tn - 1 - s) : s;
        const size_t mo = (size_t)t * Bn + bb;

        // stage h(s) fp16 into smem [b][k]
        {
            const __half* gh = g_hbf + (((size_t)(s & 1) * 2 + dir) << 15);
#pragma unroll
            for (int it = 0; it < 16; it++) {
                int i = tid + it * 256;
                int b = i >> 6, j = (i & 63) * 8;
                cpasync16(aB + (b * LAP + j) * 2, gh + b * 512 + j);
            }
            cpasync_commit();
        }

        // xw for all 4 gates (fp32 exact) — overlaps cp.async flight
        float2 xwi = __ldg((const float2*)&xwT[(xrow + 0 * Hn) * Mtot + mo]);
        float2 xwf = __ldg((const float2*)&xwT[(xrow + 1 * Hn) * Mtot + mo]);
        float2 xwg = __ldg((const float2*)&xwT[(xrow + 2 * Hn) * Mtot + mo]);
        float2 xwo = __ldg((const float2*)&xwT[(xrow + 3 * Hn) * Mtot + mo]);

        cpasync_wait0();
        __syncthreads();

        float acc0[4] = {0.f, 0.f, 0.f, 0.f};  // rows g(i), g+8(f)
        float acc1[4] = {0.f, 0.f, 0.f, 0.f};  // rows 16+g(g), 24+g(o)

#pragma unroll 8
        for (int ks = 0; ks < 32; ks++) {
            const int k0 = ks * 16;
            unsigned ah0[4], ah1[4];
            unsigned ad = aAhi + ((a_roff) * LAP + k0 + a_koff) * 2;
            ldsm4(ah0[0], ah0[1], ah0[2], ah0[3], ad);
            ldsm4(ah1[0], ah1[1], ah1[2], ah1[3], ad + 16 * LAP * 2);
            unsigned b0, b1;
            ldsm2(b0, b1, aB + ((wid * 8 + b_roff) * LAP + k0 + b_koff) * 2);

            mma16816h(acc0, ah0, b0, b1);
            mma16816h(acc1, ah1, b0, b1);
        }

        // pointwise in registers
        float i0 = sigf(acc0[0] + xwi.x);
        float i1 = sigf(acc0[1] + xwi.y);
        float f0 = sigf(acc0[2] + xwf.x);
        float f1 = sigf(acc0[3] + xwf.y);
        float gg0 = tanhfast(acc1[0] + xwg.x);
        float gg1 = tanhfast(acc1[1] + xwg.y);
        float o0 = sigf(acc1[2] + xwo.x);
        float o1 = sigf(acc1[3] + xwo.y);

        c0 = fminf(fmaxf(f0 * c0 + i0 * gg0, -100.f), 100.f);
        c1 = fminf(fmaxf(f1 * c1 + i1 * gg1, -100.f), 100.f);
        float h0 = o0 * tanhfast(c0);
        float h1 = o1 * tanhfast(c1);

        // fp16 h for next step FIRST (peers wait on this)
        {
            __half* wh = g_hbf + (((size_t)((s + 1) & 1) * 2 + dir) << 15);
            wh[(size_t)bb * 512 + u0 + g] = __float2half_rn(h0);
            wh[(size_t)(bb + 1) * 512 + u0 + g] = __float2half_rn(h1);
        }

        if (s < Tn - 1) {
            __syncthreads();                 // all h stores issued
            if (tid == 0) red_release(ctr);  // arrive (orders prior writes)
            // peer-independent fp32 output store overlaps barrier drain
            *(float2*)&outT[((size_t)dir * Hn + u0 + g) * Mtot + mo] = make_float2(h0, h1);
            if (tid == 0) {
                unsigned target = 64u * (unsigned)(s + 1);
                while (ldacq(ctr) < target) {}
            }
            __syncthreads();
        } else {
            *(float2*)&outT[((size_t)dir * Hn + u0 + g) * Mtot + mo] = make_float2(h0, h1);
        }
    }
}

// ===================== attention logits =====================
__global__ __launch_bounds__(512)
void attn_logit_kernel(const float* __restrict__ h1T, const float* __restrict__ Wa,
                       const float* __restrict__ ba, float* __restrict__ logit) {
    __shared__ float sWa[Hn];
    __shared__ float red[8][64];
    const int t = blockIdx.x;
    const int ug = threadIdx.x >> 6, b = threadIdx.x & 63;
    sWa[threadIdx.x] = Wa[threadIdx.x];
    __syncthreads();

    float acc = 0.f;
    const size_t moff = (size_t)t * Bn + b;
#pragma unroll 4
    for (int uu = 0; uu < 64; uu++) {
        int u = ug * 64 + uu;
        float hf = h1T[(size_t)u * Mtot + moff];
        float hb = h1T[((size_t)Hn + u) * Mtot + moff];
        acc += (hf + hb) * sWa[u];
    }
    red[ug][b] = acc;
    __syncthreads();
    if (ug == 0) {
        float s = ba[0];
#pragma unroll
        for (int g = 0; g < 8; g++) s += red[g][b];
        logit[t * Bn + b] = s;
    }
}

// ===================== softmax over t (CTA per b) =====================
__global__ __launch_bounds__(512)
void softmax_kernel(const float* __restrict__ logit, float* __restrict__ outp,
                    float* __restrict__ aT) {
    __shared__ float red[Tn];
    const int b = blockIdx.x, t = threadIdx.x;
    float v = logit[t * Bn + b];
    red[t] = v; __syncthreads();
    for (int st = 256; st > 0; st >>= 1) {
        if (t < st) red[t] = fmaxf(red[t], red[t + st]);
        __syncthreads();
    }
    float m = red[0]; __syncthreads();
    float e = expf(v - m);
    red[t] = e; __syncthreads();
    for (int st = 256; st > 0; st >>= 1) {
        if (t < st) red[t] += red[t + st];
        __syncthreads();
    }
    float a = e / red[0];
    outp[Bn * NOUT + b * Tn + t] = a;
    aT[t * Bn + b] = a;
}

// ===================== attention pooling (CTA per u) =====================
__global__ __launch_bounds__(64)
void pool_kernel(const float* __restrict__ h1T, const float* __restrict__ aT,
                 float* __restrict__ pooledT) {
    const int u = blockIdx.x, b = threadIdx.x;
    const float* hf = h1T + (size_t)u * Mtot;
    const float* hb = h1T + ((size_t)Hn + u) * Mtot;
    float acc = 0.f;
#pragma unroll 4
    for (int t = 0; t < Tn; t++) {
        acc += (hf[t * Bn + b] + hb[t * Bn + b]) * aT[t * Bn + b];
    }
    pooledT[u * Bn + b] = acc;
}

// ===================== output head (CTA per b) =====================
__global__ __launch_bounds__(128)
void pred_kernel(const float* __restrict__ pooledT, const float* __restrict__ Wo,
                 const float* __restrict__ bo, float* __restrict__ outp) {
    __shared__ float sp[Hn];
    const int b = blockIdx.x, o = threadIdx.x;
    for (int u = o; u < Hn; u += 128) sp[u] = pooledT[u * Bn + b];
    __syncthreads();
    float s = bo[o];
    const float* wp = Wo + (size_t)o * Hn;
#pragma unroll 4
    for (int u = 0; u < Hn; u++) s += sp[u] * wp[u];
    outp[b * NOUT + o] = s;
}

// ===================== launch =====================
extern "C" void kernel_launch(void* const* d_in, const int* in_sizes, int n_in,
                              void* d_out, int out_size) {
    (void)in_sizes; (void)n_in; (void)out_size;
    const float* input = (const float*)d_in[0];
    const float* Wih0  = (const float*)d_in[1];
    const float* Whh0  = (const float*)d_in[2];
    const float* b0    = (const float*)d_in[3];
    const float* Wih1  = (const float*)d_in[4];
    const float* Whh1  = (const float*)d_in[5];
    const float* b1    = (const float*)d_in[6];
    const float* Wa    = (const float*)d_in[7];
    const float* ba    = (const float*)d_in[8];
    const float* Wo    = (const float*)d_in[9];
    const float* bo    = (const float*)d_in[10];
    float* outp = (float*)d_out;

    float *xw, *out0, *out1, *logit, *aT, *pooledT;
    __half *xh, *wh;
    cudaGetSymbolAddress((void**)&xw, g_xw);
    cudaGetSymbolAddress((void**)&out0, g_out0);
    cudaGetSymbolAddress((void**)&out1, g_out1);
    cudaGetSymbolAddress((void**)&logit, g_logit);
    cudaGetSymbolAddress((void**)&aT, g_attnT);
    cudaGetSymbolAddress((void**)&pooledT, g_pooledT);
    cudaGetSymbolAddress((void**)&xh, g_xh);
    cudaGetSymbolAddress((void**)&wh, g_wh);

    cudaFuncSetAttribute(lstm_mma_kernel, cudaFuncAttributeMaxDynamicSharedMemorySize,
                         LSTM2_SMEM);
    cudaFuncSetAttribute(mma_gemm_kernel, cudaFuncAttributeMaxDynamicSharedMemorySize,
                         GEMM_SMEM);

    dim3 mgrid(32, 256);   // 32 n-tiles (4096/128), 256 m-tiles

    // ---- layer 0 ----
    convert_f16_kernel<<<1024, 256>>>(Wih0, wh, 2 * G4 * 256);
    convert_f16_kernel<<<2048, 256>>>(input, xh, Mtot * 256);
    mma_gemm_kernel<<<mgrid, 256, GEMM_SMEM>>>(wh, xh, b0, xw, 256);
    init_kernel<<<64, 256>>>();
    lstm_mma_kernel<<<NCTA_LSTM, 256, LSTM2_SMEM>>>(xw, Whh0, out0);

    // ---- layer 1 ----
    convert_f16_kernel<<<2048, 256>>>(Wih1, wh, 2 * G4 * 1024);
    transpose_f16_kernel<<<dim3(1024, 32), dim3(32, 8)>>>(out0, xh);
    mma_gemm_kernel<<<mgrid, 256, GEMM_SMEM>>>(wh, xh, b1, xw, 1024);
    init_kernel<<<64, 256>>>();
    lstm_mma_kernel<<<NCTA_LSTM, 256, LSTM2_SMEM>>>(xw, Whh1, out1);

    // ---- attention + head ----
    attn_logit_kernel<<<Tn, 512>>>(out1, Wa, ba, logit);
    softmax_kernel<<<Bn, Tn>>>(logit, outp, aT);
    pool_kernel<<<Hn, Bn>>>(out1, aT, pooledT);
    pred_kernel<<<Bn, NOUT>>>(pooledT, Wo, bo, outp);
}

// round 14
// speedup vs baseline: 4.6041x; 1.0111x over previous
#include <cuda_runtime.h>
#include <cuda_fp16.h>
#include <cstdint>
#include <math.h>

#define Tn   512
#define Bn   64
#define Hn   512
#define G4   2048
#define NOUT 128
#define Mtot (Tn * Bn)          // 32768
#define NCTA_LSTM 128

// ---------------- scratch ----------------
__device__ __half g_xwh[(size_t)2 * G4 * Mtot];      // xw_T[dir][n][m] fp16
__device__ float g_out1[(size_t)2 * Hn * Mtot];      // out1_T[dir][u][m] fp32 (attn input)
__device__ float g_logit[Tn * Bn];
__device__ float g_attnT[Tn * Bn];
__device__ float g_pooledT[Hn * Bn];
__device__ unsigned g_barv[64];
// h exchange buffers: [buf2][dir2][b64][k512] fp16
__device__ __half g_hbf[2 * 2 * 64 * 512];
// fp16 GEMM operands
__device__ __half g_xh[(size_t)Mtot * 1024];         // X [m][k]; layer0: k=256, layer1: k=1024 (written by lstm0)
__device__ __half g_wh0[2 * G4 * 256];
__device__ __half g_wh1[2 * G4 * 1024];

__device__ __forceinline__ unsigned ldacq(const unsigned* p) {
    unsigned v;
    asm volatile("ld.acquire.gpu.global.b32 %0, [%1];" : "=r"(v) : "l"(p) : "memory");
    return v;
}
__device__ __forceinline__ void red_release(unsigned* p) {
    asm volatile("red.release.gpu.global.add.u32 [%0], %1;" :: "l"(p), "r"(1u) : "memory");
}
__device__ __forceinline__ float sigf(float x) {
    return 1.f / (1.f + __expf(-x));
}
__device__ __forceinline__ float tanhfast(float x) {
    return 1.f - 2.f / (1.f + __expf(2.f * x));
}

// ==================== mma.sync helpers ====================
__device__ __forceinline__ unsigned smem_u32(const void* p) {
    unsigned a;
    asm("{ .reg .u64 t; cvta.to.shared.u64 t, %1; cvt.u32.u64 %0, t; }" : "=r"(a) : "l"(p));
    return a;
}
__device__ __forceinline__ void ldsm4(unsigned& r0, unsigned& r1, unsigned& r2, unsigned& r3,
                                      unsigned addr) {
    asm volatile("ldmatrix.sync.aligned.m8n8.x4.shared.b16 {%0,%1,%2,%3}, [%4];"
                 : "=r"(r0), "=r"(r1), "=r"(r2), "=r"(r3) : "r"(addr));
}
__device__ __forceinline__ void ldsm2(unsigned& r0, unsigned& r1, unsigned addr) {
    asm volatile("ldmatrix.sync.aligned.m8n8.x2.shared.b16 {%0,%1}, [%2];"
                 : "=r"(r0), "=r"(r1) : "r"(addr));
}
__device__ __forceinline__ void mma16816h(float* c, const unsigned* a, unsigned b0, unsigned b1) {
    asm volatile(
        "mma.sync.aligned.m16n8k16.row.col.f32.f16.f16.f32 "
        "{%0,%1,%2,%3}, {%4,%5,%6,%7}, {%8,%9}, {%0,%1,%2,%3};"
        : "+f"(c[0]), "+f"(c[1]), "+f"(c[2]), "+f"(c[3])
        : "r"(a[0]), "r"(a[1]), "r"(a[2]), "r"(a[3]), "r"(b0), "r"(b1));
}
__device__ __forceinline__ void cpasync16(unsigned dst, const void* src) {
    asm volatile("cp.async.cg.shared.global [%0], [%1], 16;" :: "r"(dst), "l"(src));
}
__device__ __forceinline__ void cpasync_commit() {
    asm volatile("cp.async.commit_group;" ::: "memory");
}
__device__ __forceinline__ void cpasync_wait0() {
    asm volatile("cp.async.wait_group 0;" ::: "memory");
}
__device__ __forceinline__ void cpasync_wait1() {
    asm volatile("cp.async.wait_group 1;" ::: "memory");
}

// ==================== fp32 -> fp16 converter ====================
__global__ void convert_f16_kernel(const float* __restrict__ in,
                                   __half* __restrict__ out, int n) {
    int i = blockIdx.x * blockDim.x + threadIdx.x;
    for (; i < n; i += gridDim.x * blockDim.x)
        out[i] = __float2half_rn(in[i]);
}

// ==================== fp16 mma.sync GEMM, fp16 output ====================
// C[n][m] = fp16( sum_k W[n][k] * X[m][k] + bias[n] ), fp32 accum.
#define GP      72
#define GTILE   (128 * GP * 2)          // 18432 B
#define GBUF    (2 * GTILE)             // W, X      (36864)
#define GEMM_SMEM (2 * GBUF)            // double buffer (73728)

__global__ __launch_bounds__(256, 2)
void mma_gemm_kernel(const __half* __restrict__ Wh, const __half* __restrict__ Xh,
                     const float* __restrict__ bias, __half* __restrict__ C, int K) {
    extern __shared__ char smem[];
    const unsigned sb = smem_u32(smem);
    const int tid = threadIdx.x;
    const int wid = tid >> 5, lane = tid & 31;
    const int wa = wid & 3;
    const int wb = wid >> 2;
    const int n0 = blockIdx.x * 128;
    const int m0 = blockIdx.y * 128;
    const int NC = K >> 6;

    const __half* gsrc[2] = {Wh + (size_t)n0 * K, Xh + (size_t)m0 * K};

    float acc[2][8][4];
#pragma unroll
    for (int i = 0; i < 2; i++)
#pragma unroll
        for (int j = 0; j < 8; j++)
#pragma unroll
            for (int q = 0; q < 4; q++) acc[i][j][q] = 0.f;

#pragma unroll
    for (int tgt = 0; tgt < 2; tgt++) {
#pragma unroll
        for (int i = 0; i < 4; i++) {
            int lin = tid + i * 256;
            int row = lin >> 3, unit = lin & 7;
            cpasync16(sb + tgt * GTILE + (row * GP + unit * 8) * 2,
                      gsrc[tgt] + (size_t)row * K + unit * 8);
        }
    }
    cpasync_commit();

    const int a_roff = (lane & 7) + ((lane >> 3) & 1) * 8;
    const int a_koff = ((lane >> 4) & 1) * 8;
    const int b_roff = (lane & 7) + ((lane >> 4) & 1) * 8;
    const int b_koff = ((lane >> 3) & 1) * 8;

#pragma unroll 1
    for (int c = 0; c < NC; c++) {
        cpasync_wait0();
        __syncthreads();
        if (c + 1 < NC) {
            const int kc = (c + 1) * 64;
            const unsigned bo = ((c + 1) & 1) * GBUF;
#pragma unroll
            for (int tgt = 0; tgt < 2; tgt++) {
#pragma unroll
                for (int i = 0; i < 4; i++) {
                    int lin = tid + i * 256;
                    int row = lin >> 3, unit = lin & 7;
                    cpasync16(sb + bo + tgt * GTILE + (row * GP + unit * 8) * 2,
                              gsrc[tgt] + (size_t)row * K + kc + unit * 8);
                }
            }
            cpasync_commit();
        }
        const unsigned cb = (c & 1) * GBUF;
#pragma unroll
        for (int ks = 0; ks < 4; ks++) {
            const int k0 = ks * 16;
            unsigned af[2][4], bf[4][4];
#pragma unroll
            for (int mf = 0; mf < 2; mf++) {
                int row = wa * 32 + mf * 16 + a_roff;
                ldsm4(af[mf][0], af[mf][1], af[mf][2], af[mf][3],
                      sb + cb + (row * GP + k0 + a_koff) * 2);
            }
#pragma unroll
            for (int nf = 0; nf < 4; nf++) {
                int row = wb * 64 + nf * 16 + b_roff;
                ldsm4(bf[nf][0], bf[nf][1], bf[nf][2], bf[nf][3],
                      sb + cb + GTILE + (row * GP + k0 + b_koff) * 2);
            }
#pragma unroll
            for (int mf = 0; mf < 2; mf++)
#pragma unroll
                for (int nf = 0; nf < 4; nf++)
#pragma unroll
                    for (int hf = 0; hf < 2; hf++)
                        mma16816h(acc[mf][nf * 2 + hf], af[mf],
                                  bf[nf][hf * 2], bf[nf][hf * 2 + 1]);
        }
        __syncthreads();
    }

    const int g = lane >> 2, tig = lane & 3;
#pragma unroll
    for (int mf = 0; mf < 2; mf++) {
        const int nr = n0 + wa * 32 + mf * 16 + g;
        const float bv0 = bias[nr];
        const float bv1 = bias[nr + 8];
#pragma unroll
        for (int j = 0; j < 8; j++) {
            const int mcol = m0 + wb * 64 + j * 8 + tig * 2;
            __half2 v0 = __floats2half2_rn(acc[mf][j][0] + bv0, acc[mf][j][1] + bv0);
            __half2 v1 = __floats2half2_rn(acc[mf][j][2] + bv1, acc[mf][j][3] + bv1);
            *(__half2*)&C[(size_t)nr * Mtot + mcol] = v0;
            *(__half2*)&C[(size_t)(nr + 8) * Mtot + mcol] = v1;
        }
    }
}

// ===================== init: zero h fp16 buffers + barrier counters =====================
__global__ void init_kernel() {
    int i = blockIdx.x * blockDim.x + threadIdx.x;
    if (i < 64) g_barv[i] = 0u;
    uint4* p = (uint4*)g_hbf;
    const int n = (2 * 2 * 64 * 512) / 8;
    for (int j = i; j < n; j += gridDim.x * blockDim.x)
        p[j] = make_uint4(0u, 0u, 0u, 0u);
}

// ===================== tensor-core persistent LSTM layer =====================
// OUT_F16=1: store h as fp16 [m][dir*512+u] into outH (layer-1 GEMM input layout).
// OUT_F16=0: store h as fp32 [dir*512+u][m] into outT (attention input layout).
#define LAP 520
#define LSTM2_SMEM ((32 * LAP + 64 * LAP) * 2)   // 99840 B

template <int OUT_F16>
__global__ __launch_bounds__(256, 1)
void lstm_mma_kernel(const __half* __restrict__ xwT, const float* __restrict__ Whh,
                     float* __restrict__ outT, __half* __restrict__ outH) {
    extern __shared__ __half hbuf[];
    __half* sAhi = hbuf;                    // [32][520]
    __half* sB   = sAhi + 32 * LAP;         // [64][520]

    const int tid = threadIdx.x;
    const int wid = tid >> 5, lane = tid & 31;
    const int dir = blockIdx.x >> 6;
    const int u0 = (blockIdx.x & 63) << 3;

    for (int i = tid; i < 32 * 512; i += 256) {
        int r = i >> 9, k = i & 511;
        int gate = r >> 3, ul = r & 7;
        float w = Whh[((size_t)dir * G4 + gate * Hn + u0 + ul) * Hn + k];
        sAhi[r * LAP + k] = __float2half_rn(w);
    }

    const unsigned aAhi = smem_u32(sAhi);
    const unsigned aB   = smem_u32(sB);

    const int a_roff = (lane & 7) + ((lane >> 3) & 1) * 8;
    const int a_koff = ((lane >> 4) & 1) * 8;
    const int b_roff = lane & 7;
    const int b_koff = ((lane >> 3) & 1) * 8;

    const int g = lane >> 2;             // unit-local; acc rows {g,g+8,g+16,g+24}
    const int tig = lane & 3;
    const int bb = wid * 8 + tig * 2;    // first of this thread's 2 batches

    float c0 = 0.f, c1 = 0.f;
    unsigned* ctr = &g_barv[dir * 32];
    const size_t xrow = (size_t)dir * G4 + u0 + g;

#pragma unroll 1
    for (int s = 0; s < Tn; s++) {
        const int t = dir ? (Tn - 1 - s) : s;
        const size_t mo = (size_t)t * Bn + bb;

        // stage h(s) fp16 into smem [b][k], split into two k-half cp.async groups
        {
            const __half* gh = g_hbf + (((size_t)(s & 1) * 2 + dir) << 15);
#pragma unroll
            for (int it = 0; it < 8; it++) {
                int i = tid + it * 256;
                int b = i >> 5, j = (i & 31) * 8;
                cpasync16(aB + (b * LAP + j) * 2, gh + b * 512 + j);
            }
            cpasync_commit();
#pragma unroll
            for (int it = 0; it < 8; it++) {
                int i = tid + it * 256;
                int b = i >> 5, j = 256 + (i & 31) * 8;
                cpasync16(aB + (b * LAP + j) * 2, gh + b * 512 + j);
            }
            cpasync_commit();
        }

        // xw for all 4 gates (fp16 pair -> fp32) — overlaps cp.async flight
        float2 xwi = __half22float2(__ldg((const __half2*)&xwT[(xrow + 0 * Hn) * Mtot + mo]));
        float2 xwf = __half22float2(__ldg((const __half2*)&xwT[(xrow + 1 * Hn) * Mtot + mo]));
        float2 xwg = __half22float2(__ldg((const __half2*)&xwT[(xrow + 2 * Hn) * Mtot + mo]));
        float2 xwo = __half22float2(__ldg((const __half2*)&xwT[(xrow + 3 * Hn) * Mtot + mo]));

        float acc0[4] = {0.f, 0.f, 0.f, 0.f};  // rows g(i), g+8(f)
        float acc1[4] = {0.f, 0.f, 0.f, 0.f};  // rows 16+g(g), 24+g(o)

        // first k-half ready -> compute ks 0..15 while second half lands
        cpasync_wait1();
        __syncthreads();
#pragma unroll 8
        for (int ks = 0; ks < 16; ks++) {
            const int k0 = ks * 16;
            unsigned ah0[4], ah1[4];
            unsigned ad = aAhi + ((a_roff) * LAP + k0 + a_koff) * 2;
            ldsm4(ah0[0], ah0[1], ah0[2], ah0[3], ad);
            ldsm4(ah1[0], ah1[1], ah1[2], ah1[3], ad + 16 * LAP * 2);
            unsigned b0, b1;
            ldsm2(b0, b1, aB + ((wid * 8 + b_roff) * LAP + k0 + b_koff) * 2);
            mma16816h(acc0, ah0, b0, b1);
            mma16816h(acc1, ah1, b0, b1);
        }
        cpasync_wait0();
        __syncthreads();
#pragma unroll 8
        for (int ks = 16; ks < 32; ks++) {
            const int k0 = ks * 16;
            unsigned ah0[4], ah1[4];
            unsigned ad = aAhi + ((a_roff) * LAP + k0 + a_koff) * 2;
            ldsm4(ah0[0], ah0[1], ah0[2], ah0[3], ad);
            ldsm4(ah1[0], ah1[1], ah1[2], ah1[3], ad + 16 * LAP * 2);
            unsigned b0, b1;
            ldsm2(b0, b1, aB + ((wid * 8 + b_roff) * LAP + k0 + b_koff) * 2);
            mma16816h(acc0, ah0, b0, b1);
            mma16816h(acc1, ah1, b0, b1);
        }

        // pointwise in registers
        float i0 = sigf(acc0[0] + xwi.x);
        float i1 = sigf(acc0[1] + xwi.y);
        float f0 = sigf(acc0[2] + xwf.x);
        float f1 = sigf(acc0[3] + xwf.y);
        float gg0 = tanhfast(acc1[0] + xwg.x);
        float gg1 = tanhfast(acc1[1] + xwg.y);
        float o0 = sigf(acc1[2] + xwo.x);
        float o1 = sigf(acc1[3] + xwo.y);

        c0 = fminf(fmaxf(f0 * c0 + i0 * gg0, -100.f), 100.f);
        c1 = fminf(fmaxf(f1 * c1 + i1 * gg1, -100.f), 100.f);
        float h0 = o0 * tanhfast(c0);
        float h1 = o1 * tanhfast(c1);
        __half h0h = __float2half_rn(h0);
        __half h1h = __float2half_rn(h1);

        // fp16 h for next step FIRST (peers wait on this)
        {
            __half* wh = g_hbf + (((size_t)((s + 1) & 1) * 2 + dir) << 15);
            wh[(size_t)bb * 512 + u0 + g] = h0h;
            wh[(size_t)(bb + 1) * 512 + u0 + g] = h1h;
        }

        if (s < Tn - 1) {
            __syncthreads();                 // all h stores issued
            if (tid == 0) red_release(ctr);  // arrive (orders prior writes)
            // peer-independent layer-output store overlaps barrier drain
            if (OUT_F16) {
                outH[mo * 1024 + dir * Hn + u0 + g] = h0h;
                outH[(mo + 1) * 1024 + dir * Hn + u0 + g] = h1h;
            } else {
                *(float2*)&outT[((size_t)dir * Hn + u0 + g) * Mtot + mo] = make_float2(h0, h1);
            }
            if (tid == 0) {
                unsigned target = 64u * (unsigned)(s + 1);
                while (ldacq(ctr) < target) {}
            }
            __syncthreads();
        } else {
            if (OUT_F16) {
                outH[mo * 1024 + dir * Hn + u0 + g] = h0h;
                outH[(mo + 1) * 1024 + dir * Hn + u0 + g] = h1h;
            } else {
                *(float2*)&outT[((size_t)dir * Hn + u0 + g) * Mtot + mo] = make_float2(h0, h1);
            }
        }
    }
}

// ===================== attention logits =====================
__global__ __launch_bounds__(512)
void attn_logit_kernel(const float* __restrict__ h1T, const float* __restrict__ Wa,
                       const float* __restrict__ ba, float* __restrict__ logit) {
    __shared__ float sWa[Hn];
    __shared__ float red[8][64];
    const int t = blockIdx.x;
    const int ug = threadIdx.x >> 6, b = threadIdx.x & 63;
    sWa[threadIdx.x] = Wa[threadIdx.x];
    __syncthreads();

    float acc = 0.f;
    const size_t moff = (size_t)t * Bn + b;
#pragma unroll 4
    for (int uu = 0; uu < 64; uu++) {
        int u = ug * 64 + uu;
        float hf = h1T[(size_t)u * Mtot + moff];
        float hb = h1T[((size_t)Hn + u) * Mtot + moff];
        acc += (hf + hb) * sWa[u];
    }
    red[ug][b] = acc;
    __syncthreads();
    if (ug == 0) {
        float s = ba[0];
#pragma unroll
        for (int g = 0; g < 8; g++) s += red[g][b];
        logit[t * Bn + b] = s;
    }
}

// ===================== softmax over t (CTA per b) =====================
__global__ __launch_bounds__(512)
void softmax_kernel(const float* __restrict__ logit, float* __restrict__ outp,
                    float* __restrict__ aT) {
    __shared__ float red[Tn];
    const int b = blockIdx.x, t = threadIdx.x;
    float v = logit[t * Bn + b];
    red[t] = v; __syncthreads();
    for (int st = 256; st > 0; st >>= 1) {
        if (t < st) red[t] = fmaxf(red[t], red[t + st]);
        __syncthreads();
    }
    float m = red[0]; __syncthreads();
    float e = expf(v - m);
    red[t] = e; __syncthreads();
    for (int st = 256; st > 0; st >>= 1) {
        if (t < st) red[t] += red[t + st];
        __syncthreads();
    }
    float a = e / red[0];
    outp[Bn * NOUT + b * Tn + t] = a;
    aT[t * Bn + b] = a;
}

// ===================== attention pooling (CTA per u, 512 threads) =====================
__global__ __launch_bounds__(512)
void pool_kernel(const float* __restrict__ h1T, const float* __restrict__ aT,
                 float* __restrict__ pooledT) {
    __shared__ float red[8][64];
    const int u = blockIdx.x;
    const int tt = threadIdx.x >> 6, b = threadIdx.x & 63;
    const float* hf = h1T + (size_t)u * Mtot;
    const float* hb = h1T + ((size_t)Hn + u) * Mtot;
    float acc = 0.f;
#pragma unroll 4
    for (int t = tt * 64; t < tt * 64 + 64; t++)
        acc += (hf[t * Bn + b] + hb[t * Bn + b]) * aT[t * Bn + b];
    red[tt][b] = acc;
    __syncthreads();
    if (tt == 0) {
        float s = 0.f;
#pragma unroll
        for (int g = 0; g < 8; g++) s += red[g][b];
        pooledT[u * Bn + b] = s;
    }
}

// ===================== output head (CTA per b) =====================
__global__ __launch_bounds__(128)
void pred_kernel(const float* __restrict__ pooledT, const float* __restrict__ Wo,
                 const float* __restrict__ bo, float* __restrict__ outp) {
    __shared__ float sp[Hn];
    const int b = blockIdx.x, o = threadIdx.x;
    for (int u = o; u < Hn; u += 128) sp[u] = pooledT[u * Bn + b];
    __syncthreads();
    float s = bo[o];
    const float* wp = Wo + (size_t)o * Hn;
#pragma unroll 4
    for (int u = 0; u < Hn; u++) s += sp[u] * wp[u];
    outp[b * NOUT + o] = s;
}

// ===================== launch =====================
extern "C" void kernel_launch(void* const* d_in, const int* in_sizes, int n_in,
                              void* d_out, int out_size) {
    (void)in_sizes; (void)n_in; (void)out_size;
    const float* input = (const float*)d_in[0];
    const float* Wih0  = (const float*)d_in[1];
    const float* Whh0  = (const float*)d_in[2];
    const float* b0    = (const float*)d_in[3];
    const float* Wih1  = (const float*)d_in[4];
    const float* Whh1  = (const float*)d_in[5];
    const float* b1    = (const float*)d_in[6];
    const float* Wa    = (const float*)d_in[7];
    const float* ba    = (const float*)d_in[8];
    const float* Wo    = (const float*)d_in[9];
    const float* bo    = (const float*)d_in[10];
    float* outp = (float*)d_out;

    float *out1, *logit, *aT, *pooledT;
    __half *xwh, *xh, *wh0, *wh1;
    cudaGetSymbolAddress((void**)&xwh, g_xwh);
    cudaGetSymbolAddress((void**)&out1, g_out1);
    cudaGetSymbolAddress((void**)&logit, g_logit);
    cudaGetSymbolAddress((void**)&aT, g_attnT);
    cudaGetSymbolAddress((void**)&pooledT, g_pooledT);
    cudaGetSymbolAddress((void**)&xh, g_xh);
    cudaGetSymbolAddress((void**)&wh0, g_wh0);
    cudaGetSymbolAddress((void**)&wh1, g_wh1);

    cudaFuncSetAttribute(lstm_mma_kernel<0>, cudaFuncAttributeMaxDynamicSharedMemorySize,
                         LSTM2_SMEM);
    cudaFuncSetAttribute(lstm_mma_kernel<1>, cudaFuncAttributeMaxDynamicSharedMemorySize,
                         LSTM2_SMEM);
    cudaFuncSetAttribute(mma_gemm_kernel, cudaFuncAttributeMaxDynamicSharedMemorySize,
                         GEMM_SMEM);

    dim3 mgrid(32, 256);   // 32 n-tiles (4096/128), 256 m-tiles

    // ---- layer 0 ----
    convert_f16_kernel<<<1024, 256>>>(Wih0, wh0, 2 * G4 * 256);              // 1
    convert_f16_kernel<<<2048, 256>>>(input, xh, Mtot * 256);                // 2
    mma_gemm_kernel<<<mgrid, 256, GEMM_SMEM>>>(wh0, xh, b0, xwh, 256);       // 3
    convert_f16_kernel<<<2048, 256>>>(Wih1, wh1, 2 * G4 * 1024);             // 4
    init_kernel<<<64, 256>>>();                                              // 5
    // layer-0 LSTM writes its output straight into xh as [m][dir*512+u] fp16
    lstm_mma_kernel<1><<<NCTA_LSTM, 256, LSTM2_SMEM>>>(xwh, Whh0, nullptr, xh);  // 6

    // ---- layer 1 ----
    mma_gemm_kernel<<<mgrid, 256, GEMM_SMEM>>>(wh1, xh, b1, xwh, 1024);
    init_kernel<<<64, 256>>>();
    lstm_mma_kernel<0><<<NCTA_LSTM, 256, LSTM2_SMEM>>>(xwh, Whh1, out1, nullptr);

    // ---- attention + head ----
    attn_logit_kernel<<<Tn, 512>>>(out1, Wa, ba, logit);
    softmax_kernel<<<Bn, Tn>>>(logit, outp, aT);
    pool_kernel<<<Hn, 512>>>(out1, aT, pooledT);
    pred_kernel<<<Bn, NOUT>>>(pooledT, Wo, bo, outp);
}